// round 4
// baseline (speedup 1.0000x reference)
#include <cuda_runtime.h>

#define BB 2
#define TT 2048
#define DD 1024
#define HH 16
#define DH 64

// Scratch (allowed: __device__ globals, no runtime allocation)
__device__ float g_Q[BB*TT*DD];
__device__ float g_K[BB*TT*DD];
__device__ float g_V[BB*TT*DD];
__device__ float g_O[BB*TT*DD];

__device__ __forceinline__ float* sel_buf(int s) {
    switch (s) {
        case 0: return g_Q;
        case 1: return g_K;
        case 2: return g_V;
        default: return g_O;
    }
}

// ---- packed f32x2 helpers (Blackwell FFMA2 path, PTX-only) -----------------
typedef unsigned long long u64t;

__device__ __forceinline__ u64t ffma2(u64t a, u64t b, u64t c) {
    u64t d;
    asm("fma.rn.f32x2 %0, %1, %2, %3;" : "=l"(d) : "l"(a), "l"(b), "l"(c));
    return d;
}
__device__ __forceinline__ u64t fmul2(u64t a, u64t b) {
    u64t d;
    asm("mul.rn.f32x2 %0, %1, %2;" : "=l"(d) : "l"(a), "l"(b));
    return d;
}
__device__ __forceinline__ u64t fadd2(u64t a, u64t b) {
    u64t d;
    asm("add.rn.f32x2 %0, %1, %2;" : "=l"(d) : "l"(a), "l"(b));
    return d;
}
__device__ __forceinline__ u64t pack2(float lo, float hi) {
    u64t d;
    asm("mov.b64 %0, {%1, %2};" : "=l"(d) : "f"(lo), "f"(hi));
    return d;
}
__device__ __forceinline__ void unpack2(u64t v, float& lo, float& hi) {
    asm("mov.b64 {%0, %1}, %2;" : "=f"(lo), "=f"(hi) : "l"(v));
}

union F4U2 {
    float4 f4;
    u64t   u2[2];
};

// ---------------------------------------------------------------------------
// SGEMM: C[M,N] = A[M,K] @ W[K,N] + bias[N]  (row-major fp32)
// 128x128 tile, BK=16, 8x8 per-thread, 256 threads. Inner product via FFMA2.
// ---------------------------------------------------------------------------
__global__ __launch_bounds__(256) void sgemm_bias(
    const float* __restrict__ Ap, const float* __restrict__ W,
    const float* __restrict__ bias, float* __restrict__ Cp,
    int M, int N, int K, int asel, int csel)
{
    constexpr int BM = 128, BN = 128, BK = 16, TM = 8, TN = 8;
    __shared__ float As[BK][BM];
    __shared__ float Ws[BK][BN];

    const float* A = (asel >= 0) ? sel_buf(asel) : Ap;
    float*       C = (csel >= 0) ? sel_buf(csel) : Cp;

    const int tid  = threadIdx.x;
    const int br   = blockIdx.y;
    const int bc   = blockIdx.x;
    const int trow = tid / (BN / TN);  // 0..15
    const int tcol = tid % (BN / TN);  // 0..15

    u64t acc2[TM][TN / 2];
    #pragma unroll
    for (int i = 0; i < TM; i++)
        #pragma unroll
        for (int j = 0; j < TN / 2; j++) acc2[i][j] = 0ull;

    const int aRow  = tid / (BK / 4);  // 0..63
    const int aCol4 = tid % (BK / 4);  // 0..3
    const int wRow  = tid / (BN / 4);  // 0..7
    const int wCol4 = tid % (BN / 4);  // 0..31

    const float* Ab = A + (size_t)br * BM * K;
    const float* Wb = W + bc * BN;

    for (int k0 = 0; k0 < K; k0 += BK) {
        #pragma unroll
        for (int i = 0; i < BM; i += 64) {
            float4 v = *reinterpret_cast<const float4*>(
                Ab + (size_t)(aRow + i) * K + k0 + aCol4 * 4);
            As[aCol4 * 4 + 0][aRow + i] = v.x;
            As[aCol4 * 4 + 1][aRow + i] = v.y;
            As[aCol4 * 4 + 2][aRow + i] = v.z;
            As[aCol4 * 4 + 3][aRow + i] = v.w;
        }
        #pragma unroll
        for (int i = 0; i < BK; i += 8) {
            float4 v = *reinterpret_cast<const float4*>(
                Wb + (size_t)(k0 + wRow + i) * N + wCol4 * 4);
            *reinterpret_cast<float4*>(&Ws[wRow + i][wCol4 * 4]) = v;
        }
        __syncthreads();

        #pragma unroll
        for (int kk = 0; kk < BK; kk++) {
            F4U2 a0, a1, b0, b1;
            a0.f4 = *reinterpret_cast<const float4*>(&As[kk][trow * TM]);
            a1.f4 = *reinterpret_cast<const float4*>(&As[kk][trow * TM + 4]);
            b0.f4 = *reinterpret_cast<const float4*>(&Ws[kk][tcol * TN]);
            b1.f4 = *reinterpret_cast<const float4*>(&Ws[kk][tcol * TN + 4]);
            u64t rb[4] = { b0.u2[0], b0.u2[1], b1.u2[0], b1.u2[1] };
            float ra[8] = { a0.f4.x, a0.f4.y, a0.f4.z, a0.f4.w,
                            a1.f4.x, a1.f4.y, a1.f4.z, a1.f4.w };
            #pragma unroll
            for (int i = 0; i < TM; i++) {
                const u64t ad = pack2(ra[i], ra[i]);
                #pragma unroll
                for (int j = 0; j < TN / 2; j++)
                    acc2[i][j] = ffma2(ad, rb[j], acc2[i][j]);
            }
        }
        __syncthreads();
    }

    #pragma unroll
    for (int i = 0; i < TM; i++) {
        const int row = br * BM + trow * TM + i;
        #pragma unroll
        for (int j = 0; j < TN; j += 4) {
            const int col = bc * BN + tcol * TN + j;
            float x0, x1, x2, x3;
            unpack2(acc2[i][j / 2 + 0], x0, x1);
            unpack2(acc2[i][j / 2 + 1], x2, x3);
            float4 o;
            o.x = x0 + bias[col + 0];
            o.y = x1 + bias[col + 1];
            o.z = x2 + bias[col + 2];
            o.w = x3 + bias[col + 3];
            *reinterpret_cast<float4*>(C + (size_t)row * N + col) = o;
        }
    }
}

// ---------------------------------------------------------------------------
// Flash-style attention, fp32, FFMA2 math. One query row per thread
// (q, o register-resident as packed f32x2), K/V tiles of 64 keys in smem
// (broadcast reads), online softmax with rare-rescale branch.
// Masked keys skipped (exact: exp underflows to 0 in the reference too).
// grid = (B*H, T/128), block = 128
// ---------------------------------------------------------------------------
__global__ __launch_bounds__(128) void attn_kernel(const int* __restrict__ mask)
{
    const int bh = blockIdx.x;
    const int b  = bh / HH;
    const int h  = bh % HH;
    const int r  = blockIdx.y * 128 + threadIdx.x;   // query row
    const int tid = threadIdx.x;

    __shared__ float sK[64][DH];
    __shared__ float sV[64][DH];
    __shared__ int   sM[64];

    // load q row packed, pre-scaled by 1/32 (exact power of two)
    const float* Qp = g_Q + ((size_t)b * TT + r) * DD + h * DH;
    u64t q2[32];
    #pragma unroll
    for (int d4 = 0; d4 < 16; d4++) {
        float4 v = *reinterpret_cast<const float4*>(Qp + d4 * 4);
        q2[d4 * 2 + 0] = pack2(v.x * 0.03125f, v.y * 0.03125f);
        q2[d4 * 2 + 1] = pack2(v.z * 0.03125f, v.w * 0.03125f);
    }

    u64t o2[32];
    #pragma unroll
    for (int i = 0; i < 32; i++) o2[i] = 0ull;
    float m = -1e30f, l = 0.f;

    for (int kt = 0; kt < TT; kt += 64) {
        // cooperative tile load: 64 keys x 64 dims, K and V
        for (int idx = tid; idx < 64 * 16; idx += 128) {
            const int row = idx / 16;
            const int c4  = idx % 16;
            const size_t g = ((size_t)b * TT + kt + row) * DD + h * DH + c4 * 4;
            *reinterpret_cast<float4*>(&sK[row][c4 * 4]) =
                *reinterpret_cast<const float4*>(g_K + g);
            *reinterpret_cast<float4*>(&sV[row][c4 * 4]) =
                *reinterpret_cast<const float4*>(g_V + g);
        }
        if (tid < 64) sM[tid] = mask[b * TT + kt + tid];
        __syncthreads();

        #pragma unroll 2
        for (int j = 0; j < 64; j++) {
            if (sM[j] != 0) {                 // warp-uniform: no divergence
                // dot(q, k_j) via FFMA2 with 2 independent chains for ILP
                u64t sa = 0ull, sb = 0ull;
                const float4* kr = reinterpret_cast<const float4*>(sK[j]);
                #pragma unroll
                for (int d4 = 0; d4 < 16; d4++) {
                    F4U2 kv; kv.f4 = kr[d4];
                    sa = ffma2(q2[d4 * 2 + 0], kv.u2[0], sa);
                    sb = ffma2(q2[d4 * 2 + 1], kv.u2[1], sb);
                }
                float alo, ahi, blo, bhi;
                unpack2(fadd2(sa, sb), alo, ahi);
                const float s = alo + ahi;
                (void)blo; (void)bhi;

                if (s > m) {                  // rare (O(log T) per row)
                    const float c = __expf(m - s);
                    l *= c;
                    const u64t cd = pack2(c, c);
                    #pragma unroll
                    for (int i = 0; i < 32; i++) o2[i] = fmul2(o2[i], cd);
                    m = s;
                }
                const float p = __expf(s - m);
                l += p;
                const u64t pd = pack2(p, p);
                const float4* vr = reinterpret_cast<const float4*>(sV[j]);
                #pragma unroll
                for (int d4 = 0; d4 < 16; d4++) {
                    F4U2 vv; vv.f4 = vr[d4];
                    o2[d4 * 2 + 0] = ffma2(pd, vv.u2[0], o2[d4 * 2 + 0]);
                    o2[d4 * 2 + 1] = ffma2(pd, vv.u2[1], o2[d4 * 2 + 1]);
                }
            }
        }
        __syncthreads();
    }

    const float inv = 1.f / l;
    const u64t invd = pack2(inv, inv);
    float* Op = g_O + ((size_t)b * TT + r) * DD + h * DH;
    #pragma unroll
    for (int d4 = 0; d4 < 16; d4++) {
        F4U2 ov;
        ov.u2[0] = fmul2(o2[d4 * 2 + 0], invd);
        ov.u2[1] = fmul2(o2[d4 * 2 + 1], invd);
        *reinterpret_cast<float4*>(Op + d4 * 4) = ov.f4;
    }
}

// ---------------------------------------------------------------------------
// Launch: 3 projection GEMMs -> attention -> output GEMM.
// ---------------------------------------------------------------------------
extern "C" void kernel_launch(void* const* d_in, const int* in_sizes, int n_in,
                              void* d_out, int out_size)
{
    const float* q    = (const float*)d_in[0];
    const float* k    = (const float*)d_in[1];
    const float* v    = (const float*)d_in[2];
    const int*   mask = (const int*)  d_in[3];
    const float* Wq   = (const float*)d_in[4];
    const float* bq   = (const float*)d_in[5];
    const float* Wk   = (const float*)d_in[6];
    const float* bk   = (const float*)d_in[7];
    const float* Wv   = (const float*)d_in[8];
    const float* bv   = (const float*)d_in[9];
    const float* Wo   = (const float*)d_in[10];
    const float* bo   = (const float*)d_in[11];
    float* out = (float*)d_out;

    const int M = BB * TT;   // 4096
    const int N = DD;        // 1024
    const int K = DD;        // 1024

    dim3 ggrid(N / 128, M / 128);   // (8, 32)

    sgemm_bias<<<ggrid, 256>>>(q, Wq, bq, nullptr, M, N, K, -1, 0);  // -> g_Q
    sgemm_bias<<<ggrid, 256>>>(k, Wk, bk, nullptr, M, N, K, -1, 1);  // -> g_K
    sgemm_bias<<<ggrid, 256>>>(v, Wv, bv, nullptr, M, N, K, -1, 2);  // -> g_V

    attn_kernel<<<dim3(BB * HH, TT / 128), 128>>>(mask);             // -> g_O

    sgemm_bias<<<ggrid, 256>>>(nullptr, Wo, bo, out, M, N, K, 3, -1);
}

// round 7
// speedup vs baseline: 2.3264x; 2.3264x over previous
#include <cuda_runtime.h>
#include <cuda_bf16.h>
#include <cstdint>

#define BB 2
#define TT 2048
#define DD 1024
#define HH 16
#define DH 64
#define MM (BB*TT)   // 4096

// ---------------- scratch (device globals, no runtime alloc) ----------------
__device__ float g_Q[MM*DD];
__device__ float g_K[MM*DD];
__device__ float g_V[MM*DD];
__device__ float g_O[MM*DD];
__device__ __align__(16) __nv_bfloat16 g_Ah[MM*DD];   // activation hi
__device__ __align__(16) __nv_bfloat16 g_Al[MM*DD];   // activation lo
__device__ __align__(16) __nv_bfloat16 g_Wh[DD*DD];   // W^T hi  [N][K]
__device__ __align__(16) __nv_bfloat16 g_Wl[DD*DD];   // W^T lo  [N][K]

__device__ __forceinline__ float* sel_buf(int s) {
    switch (s) {
        case 0: return g_Q;
        case 1: return g_K;
        case 2: return g_V;
        default: return g_O;
    }
}

// ---------------- PTX helpers (arch-generic: sm_80+ features only) ----------
__device__ __forceinline__ uint32_t smem_u32(const void* p) {
    uint32_t a;
    asm("{ .reg .u64 t; cvta.to.shared.u64 t, %1; cvt.u32.u64 %0, t; }" : "=r"(a) : "l"(p));
    return a;
}
__device__ __forceinline__ void cp16(uint32_t s, const void* g) {
    asm volatile("cp.async.cg.shared.global [%0], [%1], 16;" :: "r"(s), "l"(g));
}
#define CP_COMMIT() asm volatile("cp.async.commit_group;" ::: "memory")
#define CP_WAIT1()  asm volatile("cp.async.wait_group 1;" ::: "memory")
#define CP_WAIT0()  asm volatile("cp.async.wait_group 0;" ::: "memory")

__device__ __forceinline__ void ldsm4(uint32_t& r0, uint32_t& r1, uint32_t& r2,
                                      uint32_t& r3, uint32_t a) {
    asm volatile("ldmatrix.sync.aligned.m8n8.x4.shared.b16 {%0,%1,%2,%3}, [%4];"
                 : "=r"(r0), "=r"(r1), "=r"(r2), "=r"(r3) : "r"(a));
}
__device__ __forceinline__ void ldsm2(uint32_t& r0, uint32_t& r1, uint32_t a) {
    asm volatile("ldmatrix.sync.aligned.m8n8.x2.shared.b16 {%0,%1}, [%2];"
                 : "=r"(r0), "=r"(r1) : "r"(a));
}
__device__ __forceinline__ void mma16816(float* c, const uint32_t* a, const uint32_t* b) {
    asm volatile(
        "mma.sync.aligned.m16n8k16.row.col.f32.bf16.bf16.f32 "
        "{%0,%1,%2,%3}, {%4,%5,%6,%7}, {%8,%9}, {%0,%1,%2,%3};"
        : "+f"(c[0]), "+f"(c[1]), "+f"(c[2]), "+f"(c[3])
        : "r"(a[0]), "r"(a[1]), "r"(a[2]), "r"(a[3]), "r"(b[0]), "r"(b[1]));
}

// ---------------------------------------------------------------------------
// convertA: fp32 [M,K] -> bf16 hi/lo [M,K]  (elementwise, float4 granules)
// ---------------------------------------------------------------------------
__global__ __launch_bounds__(256) void convertA(const float* __restrict__ src, int sel)
{
    const float* s = (sel >= 0) ? sel_buf(sel) : src;
    const int i = (blockIdx.x * 256 + threadIdx.x) * 4;
    float4 v = *reinterpret_cast<const float4*>(s + i);

    __nv_bfloat16 h0 = __float2bfloat16_rn(v.x);
    __nv_bfloat16 h1 = __float2bfloat16_rn(v.y);
    __nv_bfloat16 h2 = __float2bfloat16_rn(v.z);
    __nv_bfloat16 h3 = __float2bfloat16_rn(v.w);
    __nv_bfloat162 hp0 = __halves2bfloat162(h0, h1);
    __nv_bfloat162 hp1 = __halves2bfloat162(h2, h3);
    uint2 ho; ho.x = *reinterpret_cast<uint32_t*>(&hp0); ho.y = *reinterpret_cast<uint32_t*>(&hp1);
    *reinterpret_cast<uint2*>(g_Ah + i) = ho;

    __nv_bfloat16 l0 = __float2bfloat16_rn(v.x - __bfloat162float(h0));
    __nv_bfloat16 l1 = __float2bfloat16_rn(v.y - __bfloat162float(h1));
    __nv_bfloat16 l2 = __float2bfloat16_rn(v.z - __bfloat162float(h2));
    __nv_bfloat16 l3 = __float2bfloat16_rn(v.w - __bfloat162float(h3));
    __nv_bfloat162 lp0 = __halves2bfloat162(l0, l1);
    __nv_bfloat162 lp1 = __halves2bfloat162(l2, l3);
    uint2 lo; lo.x = *reinterpret_cast<uint32_t*>(&lp0); lo.y = *reinterpret_cast<uint32_t*>(&lp1);
    *reinterpret_cast<uint2*>(g_Al + i) = lo;
}

// ---------------------------------------------------------------------------
// convertW: fp32 W[K,N] -> bf16 hi/lo W^T [N,K]  (tiled transpose)
// grid (N/32, K/32), block (32, 8)
// ---------------------------------------------------------------------------
__global__ __launch_bounds__(256) void convertW(const float* __restrict__ W)
{
    __shared__ float tile[32][33];
    const int n0 = blockIdx.x * 32;
    const int k0 = blockIdx.y * 32;
    const int tx = threadIdx.x, ty = threadIdx.y;

    #pragma unroll
    for (int r = 0; r < 4; r++)
        tile[ty + r * 8][tx] = W[(size_t)(k0 + ty + r * 8) * DD + n0 + tx];
    __syncthreads();

    #pragma unroll
    for (int r = 0; r < 4; r++) {
        const int n = ty + r * 8;
        const float x = tile[tx][n];
        __nv_bfloat16 h = __float2bfloat16_rn(x);
        __nv_bfloat16 l = __float2bfloat16_rn(x - __bfloat162float(h));
        const size_t o = (size_t)(n0 + n) * DD + k0 + tx;
        g_Wh[o] = h;
        g_Wl[o] = l;
    }
}

// ---------------------------------------------------------------------------
// HMMA bf16-split GEMM: C[M,N] = (Ah+Al)[M,K] @ (Wh+Wl)^T[N,K] + bias
// 128x128 CTA tile, 8 warps (64x32 each), m16n8k16, 3 split passes into the
// same fp32 accumulators. BK=32, cp.async double-buffered smem.
// smem tile rows padded to 40 bf16 (80B) -> conflict-free ldmatrix.
// ---------------------------------------------------------------------------
#define TILE_B   10240               // 128 rows * 80 bytes
#define BUF_B    (4 * TILE_B)        // Ah, Al, Bh, Bl
#define GSM_TOT  (2 * BUF_B)         // 81920 bytes

__global__ __launch_bounds__(256) void mma_gemm(
    const float* __restrict__ bias, float* __restrict__ Cp, int csel)
{
    extern __shared__ char smem[];
    const uint32_t sb = smem_u32(smem);
    const int tid  = threadIdx.x;
    const int wid  = tid >> 5;
    const int lane = tid & 31;
    const int warp_m = wid & 1;          // 0..1 -> 64 rows
    const int warp_n = wid >> 1;         // 0..3 -> 32 cols

    float* C = (csel >= 0) ? sel_buf(csel) : Cp;

    const int aBase = blockIdx.y * 128;
    const int bBase = blockIdx.x * 128;
    const __nv_bfloat16* srcs[4] = {
        g_Ah + (size_t)aBase * DD, g_Al + (size_t)aBase * DD,
        g_Wh + (size_t)bBase * DD, g_Wl + (size_t)bBase * DD };

    float acc[4][4][4];
    #pragma unroll
    for (int i = 0; i < 4; i++)
        #pragma unroll
        for (int j = 0; j < 4; j++)
            #pragma unroll
            for (int r = 0; r < 4; r++) acc[i][j][r] = 0.f;

    // ---- async tile loader: chunk c (32 k-elems) into buffer buf ----
    auto load_chunk = [&](int c, int buf) {
        const int c0 = c * 32;
        const uint32_t base = sb + buf * BUF_B;
        #pragma unroll
        for (int it = 0; it < 8; it++) {
            const int idx = tid + it * 256;        // 0..2047
            const int t4  = idx >> 9;
            const int rem = idx & 511;
            const int row = rem >> 2;
            const int seg = rem & 3;
            cp16(base + t4 * TILE_B + row * 80 + seg * 16,
                 srcs[t4] + (size_t)row * DD + c0 + seg * 8);
        }
    };

    load_chunk(0, 0);
    CP_COMMIT();

    int buf = 0;
    for (int c = 0; c < 32; c++) {
        if (c + 1 < 32) {
            load_chunk(c + 1, buf ^ 1);
            CP_COMMIT();
            CP_WAIT1();
        } else {
            CP_WAIT0();
        }
        __syncthreads();

        const uint32_t sAh = sb + buf * BUF_B;
        const uint32_t sAl = sAh + TILE_B;
        const uint32_t sBh = sAh + 2 * TILE_B;
        const uint32_t sBl = sAh + 3 * TILE_B;

        #pragma unroll
        for (int ks = 0; ks < 2; ks++) {
            const int kb = ks * 32;                          // byte offset of k16 step
            uint32_t ah[4][4], al[4][4], bh[4][2], bl[4][2];

            const int arow = (lane & 15);
            const uint32_t acol = ((lane >> 4) << 4) + kb;
            #pragma unroll
            for (int mt = 0; mt < 4; mt++) {
                const uint32_t ro = (uint32_t)(warp_m * 64 + mt * 16 + arow) * 80 + acol;
                ldsm4(ah[mt][0], ah[mt][1], ah[mt][2], ah[mt][3], sAh + ro);
                ldsm4(al[mt][0], al[mt][1], al[mt][2], al[mt][3], sAl + ro);
            }
            const int brow = (lane & 7);
            const uint32_t bcol = (((lane >> 3) & 1) << 4) + kb;
            #pragma unroll
            for (int nt = 0; nt < 4; nt++) {
                const uint32_t ro = (uint32_t)(warp_n * 32 + nt * 8 + brow) * 80 + bcol;
                ldsm2(bh[nt][0], bh[nt][1], sBh + ro);
                ldsm2(bl[nt][0], bl[nt][1], sBl + ro);
            }

            #pragma unroll
            for (int mt = 0; mt < 4; mt++)
                #pragma unroll
                for (int nt = 0; nt < 4; nt++) {
                    mma16816(acc[mt][nt], ah[mt], bh[nt]);   // Ah*Bh
                    mma16816(acc[mt][nt], ah[mt], bl[nt]);   // Ah*Bl
                    mma16816(acc[mt][nt], al[mt], bh[nt]);   // Al*Bh
                }
        }
        __syncthreads();
        buf ^= 1;
    }

    // ---- epilogue: fragment -> global with bias ----
    #pragma unroll
    for (int mt = 0; mt < 4; mt++) {
        const int row0 = aBase + warp_m * 64 + mt * 16 + (lane >> 2);
        #pragma unroll
        for (int nt = 0; nt < 4; nt++) {
            const int col = bBase + warp_n * 32 + nt * 8 + (lane & 3) * 2;
            const float b0 = bias[col], b1 = bias[col + 1];
            float2 v0 = { acc[mt][nt][0] + b0, acc[mt][nt][1] + b1 };
            float2 v1 = { acc[mt][nt][2] + b0, acc[mt][nt][3] + b1 };
            *reinterpret_cast<float2*>(C + (size_t)row0 * DD + col) = v0;
            *reinterpret_cast<float2*>(C + (size_t)(row0 + 8) * DD + col) = v1;
        }
    }
}

// ---------------------------------------------------------------------------
// Flash-style attention, fp32 (R1 kernel — known good).
// grid = (B*H, T/128), block = 128
// ---------------------------------------------------------------------------
__global__ __launch_bounds__(128) void attn_kernel(const int* __restrict__ mask)
{
    const int bh = blockIdx.x;
    const int b  = bh / HH;
    const int h  = bh % HH;
    const int r  = blockIdx.y * 128 + threadIdx.x;
    const int tid = threadIdx.x;

    __shared__ float sK[64][DH];
    __shared__ float sV[64][DH];
    __shared__ int   sM[64];

    const float* Qp = g_Q + ((size_t)b * TT + r) * DD + h * DH;
    float q[DH];
    #pragma unroll
    for (int d = 0; d < DH; d += 4) {
        float4 v = *reinterpret_cast<const float4*>(Qp + d);
        q[d + 0] = v.x * 0.03125f;
        q[d + 1] = v.y * 0.03125f;
        q[d + 2] = v.z * 0.03125f;
        q[d + 3] = v.w * 0.03125f;
    }

    float o[DH];
    #pragma unroll
    for (int d = 0; d < DH; d++) o[d] = 0.f;
    float m = -1e30f, l = 0.f;

    for (int kt = 0; kt < TT; kt += 64) {
        for (int idx = tid; idx < 64 * 16; idx += 128) {
            const int row = idx / 16;
            const int c4  = idx % 16;
            const size_t g = ((size_t)b * TT + kt + row) * DD + h * DH + c4 * 4;
            *reinterpret_cast<float4*>(&sK[row][c4 * 4]) =
                *reinterpret_cast<const float4*>(g_K + g);
            *reinterpret_cast<float4*>(&sV[row][c4 * 4]) =
                *reinterpret_cast<const float4*>(g_V + g);
        }
        if (tid < 64) sM[tid] = mask[b * TT + kt + tid];
        __syncthreads();

        #pragma unroll 2
        for (int j = 0; j < 64; j++) {
            if (sM[j] != 0) {
                float s = 0.f;
                const float4* kr = reinterpret_cast<const float4*>(sK[j]);
                #pragma unroll
                for (int d4 = 0; d4 < 16; d4++) {
                    float4 kv = kr[d4];
                    s += q[d4 * 4 + 0] * kv.x + q[d4 * 4 + 1] * kv.y
                       + q[d4 * 4 + 2] * kv.z + q[d4 * 4 + 3] * kv.w;
                }
                if (s > m) {
                    const float c = __expf(m - s);
                    l *= c;
                    #pragma unroll
                    for (int d = 0; d < DH; d++) o[d] *= c;
                    m = s;
                }
                const float p = __expf(s - m);
                l += p;
                const float4* vr = reinterpret_cast<const float4*>(sV[j]);
                #pragma unroll
                for (int d4 = 0; d4 < 16; d4++) {
                    float4 vv = vr[d4];
                    o[d4 * 4 + 0] += p * vv.x;
                    o[d4 * 4 + 1] += p * vv.y;
                    o[d4 * 4 + 2] += p * vv.z;
                    o[d4 * 4 + 3] += p * vv.w;
                }
            }
        }
        __syncthreads();
    }

    const float inv = 1.f / l;
    float* Op = g_O + ((size_t)b * TT + r) * DD + h * DH;
    #pragma unroll
    for (int d = 0; d < DH; d += 4) {
        float4 v;
        v.x = o[d + 0] * inv;
        v.y = o[d + 1] * inv;
        v.z = o[d + 2] * inv;
        v.w = o[d + 3] * inv;
        *reinterpret_cast<float4*>(Op + d) = v;
    }
}

// ---------------------------------------------------------------------------
// Launch
// ---------------------------------------------------------------------------
extern "C" void kernel_launch(void* const* d_in, const int* in_sizes, int n_in,
                              void* d_out, int out_size)
{
    const float* q    = (const float*)d_in[0];
    const float* k    = (const float*)d_in[1];
    const float* v    = (const float*)d_in[2];
    const int*   mask = (const int*)  d_in[3];
    const float* Wq   = (const float*)d_in[4];
    const float* bq   = (const float*)d_in[5];
    const float* Wk   = (const float*)d_in[6];
    const float* bk   = (const float*)d_in[7];
    const float* Wv   = (const float*)d_in[8];
    const float* bv   = (const float*)d_in[9];
    const float* Wo   = (const float*)d_in[10];
    const float* bo   = (const float*)d_in[11];
    float* out = (float*)d_out;

    cudaFuncSetAttribute(mma_gemm, cudaFuncAttributeMaxDynamicSharedMemorySize, GSM_TOT);

    const dim3 cgrid(MM * DD / 4 / 256);
    const dim3 wgrid(DD / 32, DD / 32);
    const dim3 wblk(32, 8);
    const dim3 ggrid(DD / 128, MM / 128);   // (8, 32)

    convertA<<<cgrid, 256>>>(q, -1);
    convertW<<<wgrid, wblk>>>(Wq);
    mma_gemm<<<ggrid, 256, GSM_TOT>>>(bq, nullptr, 0);   // -> g_Q

    convertA<<<cgrid, 256>>>(k, -1);
    convertW<<<wgrid, wblk>>>(Wk);
    mma_gemm<<<ggrid, 256, GSM_TOT>>>(bk, nullptr, 1);   // -> g_K

    convertA<<<cgrid, 256>>>(v, -1);
    convertW<<<wgrid, wblk>>>(Wv);
    mma_gemm<<<ggrid, 256, GSM_TOT>>>(bv, nullptr, 2);   // -> g_V

    attn_kernel<<<dim3(BB * HH, TT / 128), 128>>>(mask); // -> g_O

    convertA<<<cgrid, 256>>>(nullptr, 3);                // g_O -> bf16 split
    convertW<<<wgrid, wblk>>>(Wo);
    mma_gemm<<<ggrid, 256, GSM_TOT>>>(bo, out, -1);
}

// round 8
// speedup vs baseline: 4.1522x; 1.7848x over previous
#include <cuda_runtime.h>
#include <cuda_bf16.h>
#include <cuda_fp16.h>
#include <cstdint>

#define BB 2
#define TT 2048
#define DD 1024
#define HH 16
#define DH 64
#define MM (BB*TT)   // 4096

// ---------------- scratch (device globals, no runtime alloc) ----------------
__device__ float g_V[MM*DD];                          // V projection (fp32)
__device__ __align__(16) __nv_bfloat16 g_Ah[MM*DD];   // GEMM A hi (acts / attn out)
__device__ __align__(16) __nv_bfloat16 g_Al[MM*DD];   // GEMM A lo
__device__ __align__(16) __nv_bfloat16 g_Wh[DD*DD];   // W^T hi [N][K]
__device__ __align__(16) __nv_bfloat16 g_Wl[DD*DD];   // W^T lo
__device__ __align__(16) __half g_Qh[MM*DD];          // Q fp16 (pre-scaled 1/32)
__device__ __align__(16) __half g_Kh[MM*DD];          // K fp16
__device__ __align__(16) __nv_bfloat16 g_Vth[BB*HH*DH*TT];  // V^T hi [bh][d][t]
__device__ __align__(16) __nv_bfloat16 g_Vtl[BB*HH*DH*TT];  // V^T lo

// ---------------- PTX helpers (arch-generic sm_80+) ----------
__device__ __forceinline__ uint32_t smem_u32(const void* p) {
    uint32_t a;
    asm("{ .reg .u64 t; cvta.to.shared.u64 t, %1; cvt.u32.u64 %0, t; }" : "=r"(a) : "l"(p));
    return a;
}
__device__ __forceinline__ void cp16(uint32_t s, const void* g) {
    asm volatile("cp.async.cg.shared.global [%0], [%1], 16;" :: "r"(s), "l"(g));
}
#define CP_COMMIT() asm volatile("cp.async.commit_group;" ::: "memory")
#define CP_WAIT1()  asm volatile("cp.async.wait_group 1;" ::: "memory")
#define CP_WAIT0()  asm volatile("cp.async.wait_group 0;" ::: "memory")

__device__ __forceinline__ void ldsm4(uint32_t& r0, uint32_t& r1, uint32_t& r2,
                                      uint32_t& r3, uint32_t a) {
    asm volatile("ldmatrix.sync.aligned.m8n8.x4.shared.b16 {%0,%1,%2,%3}, [%4];"
                 : "=r"(r0), "=r"(r1), "=r"(r2), "=r"(r3) : "r"(a));
}
__device__ __forceinline__ void ldsm2(uint32_t& r0, uint32_t& r1, uint32_t a) {
    asm volatile("ldmatrix.sync.aligned.m8n8.x2.shared.b16 {%0,%1}, [%2];"
                 : "=r"(r0), "=r"(r1) : "r"(a));
}
__device__ __forceinline__ void mma_bf(float* c, const uint32_t* a, const uint32_t* b) {
    asm volatile(
        "mma.sync.aligned.m16n8k16.row.col.f32.bf16.bf16.f32 "
        "{%0,%1,%2,%3}, {%4,%5,%6,%7}, {%8,%9}, {%0,%1,%2,%3};"
        : "+f"(c[0]), "+f"(c[1]), "+f"(c[2]), "+f"(c[3])
        : "r"(a[0]), "r"(a[1]), "r"(a[2]), "r"(a[3]), "r"(b[0]), "r"(b[1]));
}
__device__ __forceinline__ void mma_fp(float* c, const uint32_t* a, const uint32_t* b) {
    asm volatile(
        "mma.sync.aligned.m16n8k16.row.col.f32.f16.f16.f32 "
        "{%0,%1,%2,%3}, {%4,%5,%6,%7}, {%8,%9}, {%0,%1,%2,%3};"
        : "+f"(c[0]), "+f"(c[1]), "+f"(c[2]), "+f"(c[3])
        : "r"(a[0]), "r"(a[1]), "r"(a[2]), "r"(a[3]), "r"(b[0]), "r"(b[1]));
}
// split a,b (fp32) into packed bf16x2 hi + lo
__device__ __forceinline__ void splitpack2(float a, float b, uint32_t& hi, uint32_t& lo) {
    __nv_bfloat16 ah = __float2bfloat16_rn(a);
    __nv_bfloat16 bh = __float2bfloat16_rn(b);
    __nv_bfloat162 h2; h2.x = ah; h2.y = bh;
    hi = *reinterpret_cast<uint32_t*>(&h2);
    __nv_bfloat162 l2;
    l2.x = __float2bfloat16_rn(a - __bfloat162float(ah));
    l2.y = __float2bfloat16_rn(b - __bfloat162float(bh));
    lo = *reinterpret_cast<uint32_t*>(&l2);
}

// ---------------------------------------------------------------------------
// convertA: fp32 [M,K] -> bf16 hi/lo (GEMM A operand)
// ---------------------------------------------------------------------------
__global__ __launch_bounds__(256) void convertA(const float* __restrict__ src)
{
    const int i = (blockIdx.x * 256 + threadIdx.x) * 4;
    float4 v = *reinterpret_cast<const float4*>(src + i);
    uint32_t h0, l0, h1, l1;
    splitpack2(v.x, v.y, h0, l0);
    splitpack2(v.z, v.w, h1, l1);
    uint2 ho = {h0, h1}, lo = {l0, l1};
    *reinterpret_cast<uint2*>(g_Ah + i) = ho;
    *reinterpret_cast<uint2*>(g_Al + i) = lo;
}

// ---------------------------------------------------------------------------
// convertW: fp32 W[K,N] -> bf16 hi/lo W^T [N,K]
// ---------------------------------------------------------------------------
__global__ __launch_bounds__(256) void convertW(const float* __restrict__ W)
{
    __shared__ float tile[32][33];
    const int n0 = blockIdx.x * 32;
    const int k0 = blockIdx.y * 32;
    const int tx = threadIdx.x, ty = threadIdx.y;

    #pragma unroll
    for (int r = 0; r < 4; r++)
        tile[ty + r * 8][tx] = W[(size_t)(k0 + ty + r * 8) * DD + n0 + tx];
    __syncthreads();

    #pragma unroll
    for (int r = 0; r < 4; r++) {
        const int n = ty + r * 8;
        const float x = tile[tx][n];
        __nv_bfloat16 h = __float2bfloat16_rn(x);
        __nv_bfloat16 l = __float2bfloat16_rn(x - __bfloat162float(h));
        const size_t o = (size_t)(n0 + n) * DD + k0 + tx;
        g_Wh[o] = h;
        g_Wl[o] = l;
    }
}

// ---------------------------------------------------------------------------
// convVt: g_V fp32 [b*T][D] -> V^T split bf16 [bh][d][t]
// grid (T/32, D/32, B), block (32, 8)
// ---------------------------------------------------------------------------
__global__ __launch_bounds__(256) void convVt()
{
    __shared__ float tile[32][33];
    const int t0 = blockIdx.x * 32;
    const int d0 = blockIdx.y * 32;
    const int b  = blockIdx.z;
    const int tx = threadIdx.x, ty = threadIdx.y;

    #pragma unroll
    for (int r = 0; r < 4; r++)
        tile[ty + r * 8][tx] = g_V[(size_t)(b * TT + t0 + ty + r * 8) * DD + d0 + tx];
    __syncthreads();

    #pragma unroll
    for (int r = 0; r < 4; r++) {
        const int dl = ty + r * 8;
        const int d  = d0 + dl;
        const int h  = d >> 6, dd = d & 63;
        const float x = tile[tx][dl];
        __nv_bfloat16 hh = __float2bfloat16_rn(x);
        __nv_bfloat16 ll = __float2bfloat16_rn(x - __bfloat162float(hh));
        const size_t o = (size_t)((b * HH + h) * DH + dd) * TT + t0 + tx;
        g_Vth[o] = hh;
        g_Vtl[o] = ll;
    }
}

// ---------------------------------------------------------------------------
// HMMA bf16-split GEMM (unchanged core from R7).
// mode: 0 -> g_Qh fp16 * 1/32;  1 -> g_Kh fp16;  2 -> g_V fp32;  3 -> Cp fp32
// ---------------------------------------------------------------------------
#define TILE_B   10240               // 128 rows * 80 bytes
#define BUF_B    (4 * TILE_B)
#define GSM_TOT  (2 * BUF_B)         // 81920

__global__ __launch_bounds__(256) void mma_gemm(
    const float* __restrict__ bias, float* __restrict__ Cp, int mode)
{
    extern __shared__ char smem[];
    const uint32_t sb = smem_u32(smem);
    const int tid  = threadIdx.x;
    const int wid  = tid >> 5;
    const int lane = tid & 31;
    const int warp_m = wid & 1;
    const int warp_n = wid >> 1;

    const int aBase = blockIdx.y * 128;
    const int bBase = blockIdx.x * 128;
    const __nv_bfloat16* srcs[4] = {
        g_Ah + (size_t)aBase * DD, g_Al + (size_t)aBase * DD,
        g_Wh + (size_t)bBase * DD, g_Wl + (size_t)bBase * DD };

    float acc[4][4][4];
    #pragma unroll
    for (int i = 0; i < 4; i++)
        #pragma unroll
        for (int j = 0; j < 4; j++)
            #pragma unroll
            for (int r = 0; r < 4; r++) acc[i][j][r] = 0.f;

    auto load_chunk = [&](int c, int buf) {
        const int c0 = c * 32;
        const uint32_t base = sb + buf * BUF_B;
        #pragma unroll
        for (int it = 0; it < 8; it++) {
            const int idx = tid + it * 256;
            const int t4  = idx >> 9;
            const int rem = idx & 511;
            const int row = rem >> 2;
            const int seg = rem & 3;
            cp16(base + t4 * TILE_B + row * 80 + seg * 16,
                 srcs[t4] + (size_t)row * DD + c0 + seg * 8);
        }
    };

    load_chunk(0, 0);
    CP_COMMIT();

    int buf = 0;
    for (int c = 0; c < 32; c++) {
        if (c + 1 < 32) {
            load_chunk(c + 1, buf ^ 1);
            CP_COMMIT();
            CP_WAIT1();
        } else {
            CP_WAIT0();
        }
        __syncthreads();

        const uint32_t sAh = sb + buf * BUF_B;
        const uint32_t sAl = sAh + TILE_B;
        const uint32_t sBh = sAh + 2 * TILE_B;
        const uint32_t sBl = sAh + 3 * TILE_B;

        #pragma unroll
        for (int ks = 0; ks < 2; ks++) {
            const int kb = ks * 32;
            uint32_t ah[4][4], al[4][4], bh[4][2], bl[4][2];

            const int arow = (lane & 15);
            const uint32_t acol = ((lane >> 4) << 4) + kb;
            #pragma unroll
            for (int mt = 0; mt < 4; mt++) {
                const uint32_t ro = (uint32_t)(warp_m * 64 + mt * 16 + arow) * 80 + acol;
                ldsm4(ah[mt][0], ah[mt][1], ah[mt][2], ah[mt][3], sAh + ro);
                ldsm4(al[mt][0], al[mt][1], al[mt][2], al[mt][3], sAl + ro);
            }
            const int brow = (lane & 7);
            const uint32_t bcol = (((lane >> 3) & 1) << 4) + kb;
            #pragma unroll
            for (int nt = 0; nt < 4; nt++) {
                const uint32_t ro = (uint32_t)(warp_n * 32 + nt * 8 + brow) * 80 + bcol;
                ldsm2(bh[nt][0], bh[nt][1], sBh + ro);
                ldsm2(bl[nt][0], bl[nt][1], sBl + ro);
            }

            #pragma unroll
            for (int mt = 0; mt < 4; mt++)
                #pragma unroll
                for (int nt = 0; nt < 4; nt++) {
                    mma_bf(acc[mt][nt], ah[mt], bh[nt]);
                    mma_bf(acc[mt][nt], ah[mt], bl[nt]);
                    mma_bf(acc[mt][nt], al[mt], bh[nt]);
                }
        }
        __syncthreads();
        buf ^= 1;
    }

    // ---- epilogue ----
    const float qs = (mode == 0) ? 0.03125f : 1.0f;
    #pragma unroll
    for (int mt = 0; mt < 4; mt++) {
        const int row0 = aBase + warp_m * 64 + mt * 16 + (lane >> 2);
        #pragma unroll
        for (int nt = 0; nt < 4; nt++) {
            const int col = bBase + warp_n * 32 + nt * 8 + (lane & 3) * 2;
            const float b0 = bias[col], b1 = bias[col + 1];
            float2 v0 = { acc[mt][nt][0] + b0, acc[mt][nt][1] + b1 };
            float2 v1 = { acc[mt][nt][2] + b0, acc[mt][nt][3] + b1 };
            if (mode >= 2) {
                float* C = (mode == 2) ? g_V : Cp;
                *reinterpret_cast<float2*>(C + (size_t)row0 * DD + col) = v0;
                *reinterpret_cast<float2*>(C + (size_t)(row0 + 8) * DD + col) = v1;
            } else {
                __half* D = (mode == 0) ? g_Qh : g_Kh;
                __half2 h0 = __floats2half2_rn(v0.x * qs, v0.y * qs);
                __half2 h1 = __floats2half2_rn(v1.x * qs, v1.y * qs);
                *reinterpret_cast<__half2*>(D + (size_t)row0 * DD + col) = h0;
                *reinterpret_cast<__half2*>(D + (size_t)(row0 + 8) * DD + col) = h1;
            }
        }
    }
}

// ---------------------------------------------------------------------------
// Tensor-core flash attention.
// grid = (T/64 qtiles, B*H), block = 128 (4 warps, 16 q-rows each).
// S = Q*K^T in fp16 (1 pass); softmax fp32 in fragments; P*V in bf16 3-pass
// split. Output written as split bf16 directly into g_Ah/g_Al.
// ---------------------------------------------------------------------------
#define APB    144            // smem row pitch bytes (72 elems)
#define OFF_K  0
#define OFF_VH 9216
#define OFF_VL 18432
#define OFF_MS 27648
#define ABUF   27904
#define ASM_TOT (2*ABUF)      // 55808

__global__ __launch_bounds__(128) void attn_mma(const int* __restrict__ mask)
{
    extern __shared__ char smema[];
    const uint32_t sb = smem_u32(smema);
    const int tid  = threadIdx.x;
    const int lane = tid & 31;
    const int w    = tid >> 5;
    const int bh   = blockIdx.y;
    const int b    = bh >> 4, h = bh & 15;
    const int q0   = blockIdx.x * 64;
    const int c0   = (lane & 3) * 2;
    const float NEGINF = -__int_as_float(0x7f800000);

    // preload Q A-frags (fp16, pre-scaled by 1/32 in GEMM epilogue)
    uint32_t qa[4][4];
    {
        const int r = q0 + w * 16 + (lane >> 2);
        const __half* Qb = g_Qh + (size_t)(b * TT + r) * DD + h * 64;
        #pragma unroll
        for (int t = 0; t < 4; t++) {
            qa[t][0] = *reinterpret_cast<const uint32_t*>(Qb + t * 16 + c0);
            qa[t][1] = *reinterpret_cast<const uint32_t*>(Qb + 8 * DD + t * 16 + c0);
            qa[t][2] = *reinterpret_cast<const uint32_t*>(Qb + t * 16 + 8 + c0);
            qa[t][3] = *reinterpret_cast<const uint32_t*>(Qb + 8 * DD + t * 16 + 8 + c0);
        }
    }

    auto load_tiles = [&](int kt, int bufsel) {
        const uint32_t base = sb + bufsel * ABUF;
        const int s0 = kt * 64;
        #pragma unroll
        for (int it = 0; it < 4; it++) {
            const int idx = tid + it * 128;       // 0..511
            const int row = idx >> 3, seg = idx & 7;
            cp16(base + OFF_K + row * APB + seg * 16,
                 g_Kh + (size_t)(b * TT + s0 + row) * DD + h * 64 + seg * 8);
            cp16(base + OFF_VH + row * APB + seg * 16,
                 g_Vth + (size_t)(bh * DH + row) * TT + s0 + seg * 8);
            cp16(base + OFF_VL + row * APB + seg * 16,
                 g_Vtl + (size_t)(bh * DH + row) * TT + s0 + seg * 8);
        }
        if (tid < 16) cp16(base + OFF_MS + tid * 16, mask + b * TT + s0 + tid * 4);
    };

    float o[8][4];
    #pragma unroll
    for (int n = 0; n < 8; n++)
        #pragma unroll
        for (int r = 0; r < 4; r++) o[n][r] = 0.f;
    float m0 = -1e30f, m1 = -1e30f, l0 = 0.f, l1 = 0.f;

    load_tiles(0, 0);
    CP_COMMIT();

    int buf = 0;
    for (int kt = 0; kt < TT / 64; kt++) {
        if (kt + 1 < TT / 64) {
            load_tiles(kt + 1, buf ^ 1);
            CP_COMMIT();
            CP_WAIT1();
        } else {
            CP_WAIT0();
        }
        __syncthreads();
        const uint32_t base = sb + buf * ABUF;

        // ---- S = Q K^T (fp16, fp32 accum) ----
        float sf[8][4];
        #pragma unroll
        for (int j = 0; j < 8; j++) {
            sf[j][0] = sf[j][1] = sf[j][2] = sf[j][3] = 0.f;
            uint32_t kA[4], kB[4];
            const uint32_t ka = base + OFF_K + (j * 8 + (lane & 7)) * APB
                              + ((lane >> 3) & 3) * 16;
            ldsm4(kA[0], kA[1], kA[2], kA[3], ka);
            ldsm4(kB[0], kB[1], kB[2], kB[3], ka + 64);
            mma_fp(sf[j], qa[0], &kA[0]);
            mma_fp(sf[j], qa[1], &kA[2]);
            mma_fp(sf[j], qa[2], &kB[0]);
            mma_fp(sf[j], qa[3], &kB[2]);
        }

        // ---- mask + online softmax (fragment-level) ----
        float p[8][4];
        float mx0 = NEGINF, mx1 = NEGINF;
        #pragma unroll
        for (int j = 0; j < 8; j++) {
            const int2 mk = *reinterpret_cast<const int2*>(
                smema + buf * ABUF + OFF_MS + (j * 8 + c0) * 4);
            sf[j][0] = mk.x ? sf[j][0] : NEGINF;
            sf[j][1] = mk.y ? sf[j][1] : NEGINF;
            sf[j][2] = mk.x ? sf[j][2] : NEGINF;
            sf[j][3] = mk.y ? sf[j][3] : NEGINF;
            mx0 = fmaxf(mx0, fmaxf(sf[j][0], sf[j][1]));
            mx1 = fmaxf(mx1, fmaxf(sf[j][2], sf[j][3]));
        }
        mx0 = fmaxf(mx0, __shfl_xor_sync(0xffffffffu, mx0, 1));
        mx0 = fmaxf(mx0, __shfl_xor_sync(0xffffffffu, mx0, 2));
        mx1 = fmaxf(mx1, __shfl_xor_sync(0xffffffffu, mx1, 1));
        mx1 = fmaxf(mx1, __shfl_xor_sync(0xffffffffu, mx1, 2));

        const float mn0 = fmaxf(m0, mx0), mn1 = fmaxf(m1, mx1);
        const float sc0 = __expf(m0 - mn0), sc1 = __expf(m1 - mn1);
        float sum0 = 0.f, sum1 = 0.f;
        #pragma unroll
        for (int j = 0; j < 8; j++) {
            p[j][0] = __expf(sf[j][0] - mn0);
            p[j][1] = __expf(sf[j][1] - mn0);
            p[j][2] = __expf(sf[j][2] - mn1);
            p[j][3] = __expf(sf[j][3] - mn1);
            sum0 += p[j][0] + p[j][1];
            sum1 += p[j][2] + p[j][3];
        }
        sum0 += __shfl_xor_sync(0xffffffffu, sum0, 1);
        sum0 += __shfl_xor_sync(0xffffffffu, sum0, 2);
        sum1 += __shfl_xor_sync(0xffffffffu, sum1, 1);
        sum1 += __shfl_xor_sync(0xffffffffu, sum1, 2);
        l0 = l0 * sc0 + sum0;
        l1 = l1 * sc1 + sum1;
        m0 = mn0;
        m1 = mn1;
        #pragma unroll
        for (int n = 0; n < 8; n++) {
            o[n][0] *= sc0; o[n][1] *= sc0;
            o[n][2] *= sc1; o[n][3] *= sc1;
        }

        // ---- pack P -> bf16 split A-frags ----
        uint32_t pha[4][4], pla[4][4];
        #pragma unroll
        for (int t = 0; t < 4; t++) {
            splitpack2(p[2*t][0],   p[2*t][1],   pha[t][0], pla[t][0]);
            splitpack2(p[2*t][2],   p[2*t][3],   pha[t][1], pla[t][1]);
            splitpack2(p[2*t+1][0], p[2*t+1][1], pha[t][2], pla[t][2]);
            splitpack2(p[2*t+1][2], p[2*t+1][3], pha[t][3], pla[t][3]);
        }

        // ---- O += P V  (bf16 3-pass split; B = V^T tiles) ----
        #pragma unroll
        for (int n = 0; n < 8; n++) {
            uint32_t vA[4], vB[4], wA[4], wB[4];
            const uint32_t va = base + OFF_VH + (n * 8 + (lane & 7)) * APB
                              + ((lane >> 3) & 3) * 16;
            const uint32_t wa = base + OFF_VL + (n * 8 + (lane & 7)) * APB
                              + ((lane >> 3) & 3) * 16;
            ldsm4(vA[0], vA[1], vA[2], vA[3], va);
            ldsm4(vB[0], vB[1], vB[2], vB[3], va + 64);
            ldsm4(wA[0], wA[1], wA[2], wA[3], wa);
            ldsm4(wB[0], wB[1], wB[2], wB[3], wa + 64);
            const uint32_t* bhf[4] = { &vA[0], &vA[2], &vB[0], &vB[2] };
            const uint32_t* blf[4] = { &wA[0], &wA[2], &wB[0], &wB[2] };
            #pragma unroll
            for (int t = 0; t < 4; t++) {
                mma_bf(o[n], pha[t], bhf[t]);
                mma_bf(o[n], pla[t], bhf[t]);
                mma_bf(o[n], pha[t], blf[t]);
            }
        }

        __syncthreads();
        buf ^= 1;
    }

    // ---- epilogue: o/l -> split bf16 directly into GEMM A buffers ----
    const float i0 = 1.f / l0, i1 = 1.f / l1;
    const int r0 = q0 + w * 16 + (lane >> 2);
    #pragma unroll
    for (int n = 0; n < 8; n++) {
        const size_t a0 = (size_t)(b * TT + r0) * DD + h * 64 + n * 8 + c0;
        const size_t a1 = a0 + 8 * DD;
        uint32_t hi, lo;
        splitpack2(o[n][0] * i0, o[n][1] * i0, hi, lo);
        *reinterpret_cast<uint32_t*>(g_Ah + a0) = hi;
        *reinterpret_cast<uint32_t*>(g_Al + a0) = lo;
        splitpack2(o[n][2] * i1, o[n][3] * i1, hi, lo);
        *reinterpret_cast<uint32_t*>(g_Ah + a1) = hi;
        *reinterpret_cast<uint32_t*>(g_Al + a1) = lo;
    }
}

// ---------------------------------------------------------------------------
// Launch
// ---------------------------------------------------------------------------
extern "C" void kernel_launch(void* const* d_in, const int* in_sizes, int n_in,
                              void* d_out, int out_size)
{
    const float* q    = (const float*)d_in[0];
    const float* k    = (const float*)d_in[1];
    const float* v    = (const float*)d_in[2];
    const int*   mask = (const int*)  d_in[3];
    const float* Wq   = (const float*)d_in[4];
    const float* bq   = (const float*)d_in[5];
    const float* Wk   = (const float*)d_in[6];
    const float* bk   = (const float*)d_in[7];
    const float* Wv   = (const float*)d_in[8];
    const float* bv   = (const float*)d_in[9];
    const float* Wo   = (const float*)d_in[10];
    const float* bo   = (const float*)d_in[11];
    float* out = (float*)d_out;

    cudaFuncSetAttribute(mma_gemm, cudaFuncAttributeMaxDynamicSharedMemorySize, GSM_TOT);
    cudaFuncSetAttribute(attn_mma, cudaFuncAttributeMaxDynamicSharedMemorySize, ASM_TOT);

    const dim3 cgrid(MM * DD / 4 / 256);
    const dim3 wgrid(DD / 32, DD / 32);
    const dim3 wblk(32, 8);
    const dim3 ggrid(DD / 128, MM / 128);
    const dim3 vgrid(TT / 32, DD / 32, BB);
    const dim3 agrid(TT / 64, BB * HH);

    convertA<<<cgrid, 256>>>(q);
    convertW<<<wgrid, wblk>>>(Wq);
    mma_gemm<<<ggrid, 256, GSM_TOT>>>(bq, nullptr, 0);   // -> g_Qh (fp16, /32)

    convertA<<<cgrid, 256>>>(k);
    convertW<<<wgrid, wblk>>>(Wk);
    mma_gemm<<<ggrid, 256, GSM_TOT>>>(bk, nullptr, 1);   // -> g_Kh (fp16)

    convertA<<<cgrid, 256>>>(v);
    convertW<<<wgrid, wblk>>>(Wv);
    mma_gemm<<<ggrid, 256, GSM_TOT>>>(bv, nullptr, 2);   // -> g_V (fp32)

    convVt<<<vgrid, wblk>>>();                           // -> g_Vth/g_Vtl

    attn_mma<<<agrid, 128, ASM_TOT>>>(mask);             // -> g_Ah/g_Al

    convertW<<<wgrid, wblk>>>(Wo);
    mma_gemm<<<ggrid, 256, GSM_TOT>>>(bo, out, 3);       // -> out (fp32)
}

// round 9
// speedup vs baseline: 5.0362x; 1.2129x over previous
#include <cuda_runtime.h>
#include <cuda_bf16.h>
#include <cuda_fp16.h>
#include <cstdint>

#define BB 2
#define TT 2048
#define DD 1024
#define HH 16
#define DH 64
#define MM (BB*TT)   // 4096

// ---------------- scratch (device globals, no runtime alloc) ----------------
__device__ float g_V[MM*DD];                              // V projection (fp32)
__device__ __align__(16) __nv_bfloat16 g_Ah[3][MM*DD];    // GEMM A hi per z
__device__ __align__(16) __nv_bfloat16 g_Al[3][MM*DD];    // GEMM A lo per z
__device__ __align__(16) __nv_bfloat16 g_Wh[4][DD*DD];    // W^T hi [slot][N][K]
__device__ __align__(16) __nv_bfloat16 g_Wl[4][DD*DD];    // W^T lo
__device__ __align__(16) __half g_Qh[MM*DD];              // Q fp16 (pre-scaled 1/32)
__device__ __align__(16) __half g_Kh[MM*DD];              // K fp16
__device__ __align__(16) __nv_bfloat16 g_Vth[BB*HH*DH*TT];// V^T hi [bh][d][t] (compacted t)
__device__ __align__(16) __nv_bfloat16 g_Vtl[BB*HH*DH*TT];// V^T lo
__device__ int g_idx[BB*TT];                              // compacted key -> orig t
__device__ __align__(16) int g_vmask[BB*TT];              // 1 if compacted pos valid
__device__ int g_ntiles[BB];                              // ceil(count/64)

// ---------------- PTX helpers (arch-generic sm_80+) ----------
__device__ __forceinline__ uint32_t smem_u32(const void* p) {
    uint32_t a;
    asm("{ .reg .u64 t; cvta.to.shared.u64 t, %1; cvt.u32.u64 %0, t; }" : "=r"(a) : "l"(p));
    return a;
}
__device__ __forceinline__ void cp16(uint32_t s, const void* g) {
    asm volatile("cp.async.cg.shared.global [%0], [%1], 16;" :: "r"(s), "l"(g));
}
#define CP_COMMIT() asm volatile("cp.async.commit_group;" ::: "memory")
#define CP_WAIT1()  asm volatile("cp.async.wait_group 1;" ::: "memory")
#define CP_WAIT0()  asm volatile("cp.async.wait_group 0;" ::: "memory")

__device__ __forceinline__ void ldsm4(uint32_t& r0, uint32_t& r1, uint32_t& r2,
                                      uint32_t& r3, uint32_t a) {
    asm volatile("ldmatrix.sync.aligned.m8n8.x4.shared.b16 {%0,%1,%2,%3}, [%4];"
                 : "=r"(r0), "=r"(r1), "=r"(r2), "=r"(r3) : "r"(a));
}
__device__ __forceinline__ void ldsm2(uint32_t& r0, uint32_t& r1, uint32_t a) {
    asm volatile("ldmatrix.sync.aligned.m8n8.x2.shared.b16 {%0,%1}, [%2];"
                 : "=r"(r0), "=r"(r1) : "r"(a));
}
__device__ __forceinline__ void mma_bf(float* c, const uint32_t* a, const uint32_t* b) {
    asm volatile(
        "mma.sync.aligned.m16n8k16.row.col.f32.bf16.bf16.f32 "
        "{%0,%1,%2,%3}, {%4,%5,%6,%7}, {%8,%9}, {%0,%1,%2,%3};"
        : "+f"(c[0]), "+f"(c[1]), "+f"(c[2]), "+f"(c[3])
        : "r"(a[0]), "r"(a[1]), "r"(a[2]), "r"(a[3]), "r"(b[0]), "r"(b[1]));
}
__device__ __forceinline__ void mma_fp(float* c, const uint32_t* a, const uint32_t* b) {
    asm volatile(
        "mma.sync.aligned.m16n8k16.row.col.f32.f16.f16.f32 "
        "{%0,%1,%2,%3}, {%4,%5,%6,%7}, {%8,%9}, {%0,%1,%2,%3};"
        : "+f"(c[0]), "+f"(c[1]), "+f"(c[2]), "+f"(c[3])
        : "r"(a[0]), "r"(a[1]), "r"(a[2]), "r"(a[3]), "r"(b[0]), "r"(b[1]));
}
__device__ __forceinline__ void splitpack2(float a, float b, uint32_t& hi, uint32_t& lo) {
    __nv_bfloat16 ah = __float2bfloat16_rn(a);
    __nv_bfloat16 bh = __float2bfloat16_rn(b);
    __nv_bfloat162 h2; h2.x = ah; h2.y = bh;
    hi = *reinterpret_cast<uint32_t*>(&h2);
    __nv_bfloat162 l2;
    l2.x = __float2bfloat16_rn(a - __bfloat162float(ah));
    l2.y = __float2bfloat16_rn(b - __bfloat162float(bh));
    lo = *reinterpret_cast<uint32_t*>(&l2);
}

// ---------------------------------------------------------------------------
// convertA3: fp32 q/k/v -> bf16 hi/lo slots 0/1/2.  grid (MM*DD/1024, 1, 3)
// ---------------------------------------------------------------------------
__global__ __launch_bounds__(256) void convertA3(
    const float* __restrict__ q, const float* __restrict__ k,
    const float* __restrict__ v)
{
    const int z = blockIdx.z;
    const float* src = (z == 0) ? q : (z == 1) ? k : v;
    const int i = (blockIdx.x * 256 + threadIdx.x) * 4;
    float4 x = *reinterpret_cast<const float4*>(src + i);
    uint32_t h0, l0, h1, l1;
    splitpack2(x.x, x.y, h0, l0);
    splitpack2(x.z, x.w, h1, l1);
    uint2 ho = {h0, h1}, lo = {l0, l1};
    *reinterpret_cast<uint2*>(&g_Ah[z][i]) = ho;
    *reinterpret_cast<uint2*>(&g_Al[z][i]) = lo;
}

// ---------------------------------------------------------------------------
// convertW4: fp32 W[K,N] -> bf16 hi/lo W^T [N,K], slots 0..3.
// grid (DD/32, DD/32, 4), block (32, 8)
// ---------------------------------------------------------------------------
__global__ __launch_bounds__(256) void convertW4(
    const float* __restrict__ Wq, const float* __restrict__ Wk,
    const float* __restrict__ Wv, const float* __restrict__ Wo)
{
    __shared__ float tile[32][33];
    const int z = blockIdx.z;
    const float* W = (z == 0) ? Wq : (z == 1) ? Wk : (z == 2) ? Wv : Wo;
    const int n0 = blockIdx.x * 32;
    const int k0 = blockIdx.y * 32;
    const int tx = threadIdx.x, ty = threadIdx.y;

    #pragma unroll
    for (int r = 0; r < 4; r++)
        tile[ty + r * 8][tx] = W[(size_t)(k0 + ty + r * 8) * DD + n0 + tx];
    __syncthreads();

    #pragma unroll
    for (int r = 0; r < 4; r++) {
        const int n = ty + r * 8;
        const float x = tile[tx][n];
        __nv_bfloat16 h = __float2bfloat16_rn(x);
        __nv_bfloat16 l = __float2bfloat16_rn(x - __bfloat162float(h));
        const size_t o = (size_t)(n0 + n) * DD + k0 + tx;
        g_Wh[z][o] = h;
        g_Wl[z][o] = l;
    }
}

// ---------------------------------------------------------------------------
// build_idx: deterministic per-batch compaction of valid keys.
// grid = BB, block = 512 (4 mask elems per thread).
// ---------------------------------------------------------------------------
__global__ __launch_bounds__(512) void build_idx(const int* __restrict__ mask)
{
    __shared__ int wsum[16];
    __shared__ int s_cnt;
    const int b = blockIdx.x, tid = threadIdx.x;
    const int lane = tid & 31, wid = tid >> 5;

    int m[4];
    const int base = b * TT + tid * 4;
    #pragma unroll
    for (int i = 0; i < 4; i++) m[i] = (mask[base + i] != 0) ? 1 : 0;
    const int tot = m[0] + m[1] + m[2] + m[3];

    int scan = tot;                                   // warp-inclusive scan
    #pragma unroll
    for (int ofs = 1; ofs < 32; ofs <<= 1) {
        int v = __shfl_up_sync(0xffffffffu, scan, ofs);
        if (lane >= ofs) scan += v;
    }
    if (lane == 31) wsum[wid] = scan;
    __syncthreads();
    if (wid == 0) {
        int v = (lane < 16) ? wsum[lane] : 0;
        #pragma unroll
        for (int ofs = 1; ofs < 16; ofs <<= 1) {
            int t = __shfl_up_sync(0xffffffffu, v, ofs);
            if (lane >= ofs) v += t;
        }
        if (lane < 16) wsum[lane] = v;                // inclusive warp totals
        if (lane == 15) s_cnt = v;
    }
    __syncthreads();

    int off = ((wid == 0) ? 0 : wsum[wid - 1]) + scan - tot;
    #pragma unroll
    for (int i = 0; i < 4; i++)
        if (m[i]) g_idx[b * TT + off++] = tid * 4 + i;

    const int cnt = s_cnt;
    #pragma unroll
    for (int i = 0; i < 4; i++) {
        const int j = tid * 4 + i;
        g_vmask[b * TT + j] = (j < cnt) ? 1 : 0;
        if (j >= cnt) g_idx[b * TT + j] = 0;
    }
    if (tid == 0) g_ntiles[b] = (cnt + 63) >> 6;
}

// ---------------------------------------------------------------------------
// convVt: g_V fp32 -> COMPACTED V^T split bf16 [bh][d][t_compact]
// grid (T/32, D/32, B), block (32, 8)
// ---------------------------------------------------------------------------
__global__ __launch_bounds__(256) void convVt()
{
    __shared__ float tile[32][33];
    const int t0 = blockIdx.x * 32;
    const int b  = blockIdx.z;
    if (t0 >= g_ntiles[b] * 64) return;               // beyond padded count: unused
    const int d0 = blockIdx.y * 32;
    const int tx = threadIdx.x, ty = threadIdx.y;

    #pragma unroll
    for (int r = 0; r < 4; r++) {
        const int tsrc = g_idx[b * TT + t0 + ty + r * 8];
        tile[ty + r * 8][tx] = g_V[(size_t)(b * TT + tsrc) * DD + d0 + tx];
    }
    __syncthreads();

    #pragma unroll
    for (int r = 0; r < 4; r++) {
        const int dl = ty + r * 8;
        const int d  = d0 + dl;
        const int h  = d >> 6, dd = d & 63;
        const float x = tile[tx][dl];
        __nv_bfloat16 hh = __float2bfloat16_rn(x);
        __nv_bfloat16 ll = __float2bfloat16_rn(x - __bfloat162float(hh));
        const size_t o = (size_t)((b * HH + h) * DH + dd) * TT + t0 + tx;
        g_Vth[o] = hh;
        g_Vtl[o] = ll;
    }
}

// ---------------------------------------------------------------------------
// HMMA bf16-split GEMM.  final=0: grid (8,32,3), z selects q/k/v slot.
// final=1: grid (8,32,1), A slot 0 (attn out), W slot 3, fp32 out.
// ---------------------------------------------------------------------------
#define TILE_B   10240               // 128 rows * 80 bytes
#define BUF_B    (4 * TILE_B)
#define GSM_TOT  (2 * BUF_B)         // 81920

__global__ __launch_bounds__(256) void mma_gemm(
    const float* __restrict__ b0, const float* __restrict__ b1,
    const float* __restrict__ b2, float* __restrict__ Cp, int final_)
{
    extern __shared__ char smem[];
    const uint32_t sb = smem_u32(smem);
    const int tid  = threadIdx.x;
    const int wid  = tid >> 5;
    const int lane = tid & 31;
    const int warp_m = wid & 1;
    const int warp_n = wid >> 1;

    const int z    = final_ ? 0 : blockIdx.z;
    const int ws   = final_ ? 3 : z;
    const int mode = final_ ? 3 : z;    // 0->Qh(/32), 1->Kh, 2->V fp32, 3->Cp
    const float* bias = (final_ || z == 0) ? b0 : (z == 1 ? b1 : b2);

    const int aBase = blockIdx.y * 128;
    const int bBase = blockIdx.x * 128;
    const __nv_bfloat16* srcs[4] = {
        g_Ah[z] + (size_t)aBase * DD, g_Al[z] + (size_t)aBase * DD,
        g_Wh[ws] + (size_t)bBase * DD, g_Wl[ws] + (size_t)bBase * DD };

    float acc[4][4][4];
    #pragma unroll
    for (int i = 0; i < 4; i++)
        #pragma unroll
        for (int j = 0; j < 4; j++)
            #pragma unroll
            for (int r = 0; r < 4; r++) acc[i][j][r] = 0.f;

    auto load_chunk = [&](int c, int buf) {
        const int c0 = c * 32;
        const uint32_t base = sb + buf * BUF_B;
        #pragma unroll
        for (int it = 0; it < 8; it++) {
            const int idx = tid + it * 256;
            const int t4  = idx >> 9;
            const int rem = idx & 511;
            const int row = rem >> 2;
            const int seg = rem & 3;
            cp16(base + t4 * TILE_B + row * 80 + seg * 16,
                 srcs[t4] + (size_t)row * DD + c0 + seg * 8);
        }
    };

    load_chunk(0, 0);
    CP_COMMIT();

    int buf = 0;
    for (int c = 0; c < 32; c++) {
        if (c + 1 < 32) {
            load_chunk(c + 1, buf ^ 1);
            CP_COMMIT();
            CP_WAIT1();
        } else {
            CP_WAIT0();
        }
        __syncthreads();

        const uint32_t sAh = sb + buf * BUF_B;
        const uint32_t sAl = sAh + TILE_B;
        const uint32_t sBh = sAh + 2 * TILE_B;
        const uint32_t sBl = sAh + 3 * TILE_B;

        #pragma unroll
        for (int ks = 0; ks < 2; ks++) {
            const int kb = ks * 32;
            uint32_t ah[4][4], al[4][4], bh[4][2], bl[4][2];

            const int arow = (lane & 15);
            const uint32_t acol = ((lane >> 4) << 4) + kb;
            #pragma unroll
            for (int mt = 0; mt < 4; mt++) {
                const uint32_t ro = (uint32_t)(warp_m * 64 + mt * 16 + arow) * 80 + acol;
                ldsm4(ah[mt][0], ah[mt][1], ah[mt][2], ah[mt][3], sAh + ro);
                ldsm4(al[mt][0], al[mt][1], al[mt][2], al[mt][3], sAl + ro);
            }
            const int brow = (lane & 7);
            const uint32_t bcol = (((lane >> 3) & 1) << 4) + kb;
            #pragma unroll
            for (int nt = 0; nt < 4; nt++) {
                const uint32_t ro = (uint32_t)(warp_n * 32 + nt * 8 + brow) * 80 + bcol;
                ldsm2(bh[nt][0], bh[nt][1], sBh + ro);
                ldsm2(bl[nt][0], bl[nt][1], sBl + ro);
            }

            #pragma unroll
            for (int mt = 0; mt < 4; mt++)
                #pragma unroll
                for (int nt = 0; nt < 4; nt++) {
                    mma_bf(acc[mt][nt], ah[mt], bh[nt]);
                    mma_bf(acc[mt][nt], ah[mt], bl[nt]);
                    mma_bf(acc[mt][nt], al[mt], bh[nt]);
                }
        }
        __syncthreads();
        buf ^= 1;
    }

    // ---- epilogue ----
    const float qs = (mode == 0) ? 0.03125f : 1.0f;
    #pragma unroll
    for (int mt = 0; mt < 4; mt++) {
        const int row0 = aBase + warp_m * 64 + mt * 16 + (lane >> 2);
        #pragma unroll
        for (int nt = 0; nt < 4; nt++) {
            const int col = bBase + warp_n * 32 + nt * 8 + (lane & 3) * 2;
            const float bb0 = bias[col], bb1 = bias[col + 1];
            float2 v0 = { acc[mt][nt][0] + bb0, acc[mt][nt][1] + bb1 };
            float2 v1 = { acc[mt][nt][2] + bb0, acc[mt][nt][3] + bb1 };
            if (mode >= 2) {
                float* C = (mode == 2) ? g_V : Cp;
                *reinterpret_cast<float2*>(C + (size_t)row0 * DD + col) = v0;
                *reinterpret_cast<float2*>(C + (size_t)(row0 + 8) * DD + col) = v1;
            } else {
                __half* D = (mode == 0) ? g_Qh : g_Kh;
                __half2 h0 = __floats2half2_rn(v0.x * qs, v0.y * qs);
                __half2 h1 = __floats2half2_rn(v1.x * qs, v1.y * qs);
                *reinterpret_cast<__half2*>(D + (size_t)row0 * DD + col) = h0;
                *reinterpret_cast<__half2*>(D + (size_t)(row0 + 8) * DD + col) = h1;
            }
        }
    }
}

// ---------------------------------------------------------------------------
// Tensor-core flash attention over COMPACTED keys.
// grid = (T/64 qtiles, B*H), block = 128 (4 warps, 16 q-rows each).
// K rows gathered through g_idx; V^T already compacted; padded tail masked
// by g_vmask (exp -> exactly 0). Output -> split bf16 into g_Ah[0]/g_Al[0].
// ---------------------------------------------------------------------------
#define APB    144            // smem row pitch bytes (72 elems)
#define OFF_K  0
#define OFF_VH 9216
#define OFF_VL 18432
#define OFF_MS 27648
#define ABUF   27904
#define ASM_TOT (2*ABUF)      // 55808

__global__ __launch_bounds__(128) void attn_mma()
{
    extern __shared__ char smema[];
    const uint32_t sb = smem_u32(smema);
    const int tid  = threadIdx.x;
    const int lane = tid & 31;
    const int w    = tid >> 5;
    const int bh   = blockIdx.y;
    const int b    = bh >> 4, h = bh & 15;
    const int q0   = blockIdx.x * 64;
    const int c0   = (lane & 3) * 2;
    const float NEGINF = -__int_as_float(0x7f800000);

    const int ntk = g_ntiles[b];
    const int* idxb = g_idx + b * TT;

    // preload Q A-frags (fp16, pre-scaled 1/32)
    uint32_t qa[4][4];
    {
        const int r = q0 + w * 16 + (lane >> 2);
        const __half* Qb = g_Qh + (size_t)(b * TT + r) * DD + h * 64;
        #pragma unroll
        for (int t = 0; t < 4; t++) {
            qa[t][0] = *reinterpret_cast<const uint32_t*>(Qb + t * 16 + c0);
            qa[t][1] = *reinterpret_cast<const uint32_t*>(Qb + 8 * DD + t * 16 + c0);
            qa[t][2] = *reinterpret_cast<const uint32_t*>(Qb + t * 16 + 8 + c0);
            qa[t][3] = *reinterpret_cast<const uint32_t*>(Qb + 8 * DD + t * 16 + 8 + c0);
        }
    }

    auto load_tiles = [&](int kt, int bufsel) {
        const uint32_t base = sb + bufsel * ABUF;
        const int s0 = kt * 64;
        #pragma unroll
        for (int it = 0; it < 4; it++) {
            const int idx = tid + it * 128;       // 0..511
            const int row = idx >> 3, seg = idx & 7;
            const int src = idxb[s0 + row];       // gather K through compaction idx
            cp16(base + OFF_K + row * APB + seg * 16,
                 g_Kh + (size_t)(b * TT + src) * DD + h * 64 + seg * 8);
            cp16(base + OFF_VH + row * APB + seg * 16,
                 g_Vth + (size_t)(bh * DH + row) * TT + s0 + seg * 8);
            cp16(base + OFF_VL + row * APB + seg * 16,
                 g_Vtl + (size_t)(bh * DH + row) * TT + s0 + seg * 8);
        }
        if (tid < 16) cp16(base + OFF_MS + tid * 16, g_vmask + b * TT + s0 + tid * 4);
    };

    float o[8][4];
    #pragma unroll
    for (int n = 0; n < 8; n++)
        #pragma unroll
        for (int r = 0; r < 4; r++) o[n][r] = 0.f;
    float m0 = -1e30f, m1 = -1e30f, l0 = 0.f, l1 = 0.f;

    load_tiles(0, 0);
    CP_COMMIT();

    int buf = 0;
    for (int kt = 0; kt < ntk; kt++) {
        if (kt + 1 < ntk) {
            load_tiles(kt + 1, buf ^ 1);
            CP_COMMIT();
            CP_WAIT1();
        } else {
            CP_WAIT0();
        }
        __syncthreads();
        const uint32_t base = sb + buf * ABUF;

        // ---- S = Q K^T (fp16, fp32 accum) ----
        float sf[8][4];
        #pragma unroll
        for (int j = 0; j < 8; j++) {
            sf[j][0] = sf[j][1] = sf[j][2] = sf[j][3] = 0.f;
            uint32_t kA[4], kB[4];
            const uint32_t ka = base + OFF_K + (j * 8 + (lane & 7)) * APB
                              + ((lane >> 3) & 3) * 16;
            ldsm4(kA[0], kA[1], kA[2], kA[3], ka);
            ldsm4(kB[0], kB[1], kB[2], kB[3], ka + 64);
            mma_fp(sf[j], qa[0], &kA[0]);
            mma_fp(sf[j], qa[1], &kA[2]);
            mma_fp(sf[j], qa[2], &kB[0]);
            mma_fp(sf[j], qa[3], &kB[2]);
        }

        // ---- mask padded tail + online softmax ----
        float p[8][4];
        float mx0 = NEGINF, mx1 = NEGINF;
        #pragma unroll
        for (int j = 0; j < 8; j++) {
            const int2 mk = *reinterpret_cast<const int2*>(
                smema + buf * ABUF + OFF_MS + (j * 8 + c0) * 4);
            sf[j][0] = mk.x ? sf[j][0] : NEGINF;
            sf[j][1] = mk.y ? sf[j][1] : NEGINF;
            sf[j][2] = mk.x ? sf[j][2] : NEGINF;
            sf[j][3] = mk.y ? sf[j][3] : NEGINF;
            mx0 = fmaxf(mx0, fmaxf(sf[j][0], sf[j][1]));
            mx1 = fmaxf(mx1, fmaxf(sf[j][2], sf[j][3]));
        }
        mx0 = fmaxf(mx0, __shfl_xor_sync(0xffffffffu, mx0, 1));
        mx0 = fmaxf(mx0, __shfl_xor_sync(0xffffffffu, mx0, 2));
        mx1 = fmaxf(mx1, __shfl_xor_sync(0xffffffffu, mx1, 1));
        mx1 = fmaxf(mx1, __shfl_xor_sync(0xffffffffu, mx1, 2));

        const float mn0 = fmaxf(m0, mx0), mn1 = fmaxf(m1, mx1);
        const float sc0 = __expf(m0 - mn0), sc1 = __expf(m1 - mn1);
        float sum0 = 0.f, sum1 = 0.f;
        #pragma unroll
        for (int j = 0; j < 8; j++) {
            p[j][0] = __expf(sf[j][0] - mn0);
            p[j][1] = __expf(sf[j][1] - mn0);
            p[j][2] = __expf(sf[j][2] - mn1);
            p[j][3] = __expf(sf[j][3] - mn1);
            sum0 += p[j][0] + p[j][1];
            sum1 += p[j][2] + p[j][3];
        }
        sum0 += __shfl_xor_sync(0xffffffffu, sum0, 1);
        sum0 += __shfl_xor_sync(0xffffffffu, sum0, 2);
        sum1 += __shfl_xor_sync(0xffffffffu, sum1, 1);
        sum1 += __shfl_xor_sync(0xffffffffu, sum1, 2);
        l0 = l0 * sc0 + sum0;
        l1 = l1 * sc1 + sum1;
        m0 = mn0;
        m1 = mn1;
        #pragma unroll
        for (int n = 0; n < 8; n++) {
            o[n][0] *= sc0; o[n][1] *= sc0;
            o[n][2] *= sc1; o[n][3] *= sc1;
        }

        // ---- pack P -> bf16 split A-frags ----
        uint32_t pha[4][4], pla[4][4];
        #pragma unroll
        for (int t = 0; t < 4; t++) {
            splitpack2(p[2*t][0],   p[2*t][1],   pha[t][0], pla[t][0]);
            splitpack2(p[2*t][2],   p[2*t][3],   pha[t][1], pla[t][1]);
            splitpack2(p[2*t+1][0], p[2*t+1][1], pha[t][2], pla[t][2]);
            splitpack2(p[2*t+1][2], p[2*t+1][3], pha[t][3], pla[t][3]);
        }

        // ---- O += P V  (bf16 3-pass split) ----
        #pragma unroll
        for (int n = 0; n < 8; n++) {
            uint32_t vA[4], vB[4], wA[4], wB[4];
            const uint32_t va = base + OFF_VH + (n * 8 + (lane & 7)) * APB
                              + ((lane >> 3) & 3) * 16;
            const uint32_t wa = base + OFF_VL + (n * 8 + (lane & 7)) * APB
                              + ((lane >> 3) & 3) * 16;
            ldsm4(vA[0], vA[1], vA[2], vA[3], va);
            ldsm4(vB[0], vB[1], vB[2], vB[3], va + 64);
            ldsm4(wA[0], wA[1], wA[2], wA[3], wa);
            ldsm4(wB[0], wB[1], wB[2], wB[3], wa + 64);
            const uint32_t* bhf[4] = { &vA[0], &vA[2], &vB[0], &vB[2] };
            const uint32_t* blf[4] = { &wA[0], &wA[2], &wB[0], &wB[2] };
            #pragma unroll
            for (int t = 0; t < 4; t++) {
                mma_bf(o[n], pha[t], bhf[t]);
                mma_bf(o[n], pla[t], bhf[t]);
                mma_bf(o[n], pha[t], blf[t]);
            }
        }

        __syncthreads();
        buf ^= 1;
    }

    // ---- epilogue: o/l -> split bf16 directly into GEMM A slot 0 ----
    const float i0 = 1.f / l0, i1 = 1.f / l1;
    const int r0 = q0 + w * 16 + (lane >> 2);
    #pragma unroll
    for (int n = 0; n < 8; n++) {
        const size_t a0 = (size_t)(b * TT + r0) * DD + h * 64 + n * 8 + c0;
        const size_t a1 = a0 + 8 * DD;
        uint32_t hi, lo;
        splitpack2(o[n][0] * i0, o[n][1] * i0, hi, lo);
        *reinterpret_cast<uint32_t*>(&g_Ah[0][a0]) = hi;
        *reinterpret_cast<uint32_t*>(&g_Al[0][a0]) = lo;
        splitpack2(o[n][2] * i1, o[n][3] * i1, hi, lo);
        *reinterpret_cast<uint32_t*>(&g_Ah[0][a1]) = hi;
        *reinterpret_cast<uint32_t*>(&g_Al[0][a1]) = lo;
    }
}

// ---------------------------------------------------------------------------
// Launch
// ---------------------------------------------------------------------------
extern "C" void kernel_launch(void* const* d_in, const int* in_sizes, int n_in,
                              void* d_out, int out_size)
{
    const float* q    = (const float*)d_in[0];
    const float* k    = (const float*)d_in[1];
    const float* v    = (const float*)d_in[2];
    const int*   mask = (const int*)  d_in[3];
    const float* Wq   = (const float*)d_in[4];
    const float* bq   = (const float*)d_in[5];
    const float* Wk   = (const float*)d_in[6];
    const float* bk   = (const float*)d_in[7];
    const float* Wv   = (const float*)d_in[8];
    const float* bv   = (const float*)d_in[9];
    const float* Wo   = (const float*)d_in[10];
    const float* bo   = (const float*)d_in[11];
    float* out = (float*)d_out;

    cudaFuncSetAttribute(mma_gemm, cudaFuncAttributeMaxDynamicSharedMemorySize, GSM_TOT);
    cudaFuncSetAttribute(attn_mma, cudaFuncAttributeMaxDynamicSharedMemorySize, ASM_TOT);

    const dim3 cgrid(MM * DD / 4 / 256, 1, 3);
    const dim3 wgrid(DD / 32, DD / 32, 4);
    const dim3 wblk(32, 8);
    const dim3 pgrid(DD / 128, MM / 128, 3);   // batched projections
    const dim3 fgrid(DD / 128, MM / 128, 1);   // final GEMM
    const dim3 vgrid(TT / 32, DD / 32, BB);
    const dim3 agrid(TT / 64, BB * HH);

    convertW4<<<wgrid, wblk>>>(Wq, Wk, Wv, Wo);              // all W^T splits
    convertA3<<<cgrid, 256>>>(q, k, v);                      // all A splits
    build_idx<<<BB, 512>>>(mask);                            // key compaction

    mma_gemm<<<pgrid, 256, GSM_TOT>>>(bq, bk, bv, nullptr, 0); // Qh, Kh, V

    convVt<<<vgrid, wblk>>>();                               // compacted V^T

    attn_mma<<<agrid, 128, ASM_TOT>>>();                     // -> g_Ah[0]/g_Al[0]

    mma_gemm<<<fgrid, 256, GSM_TOT>>>(bo, bo, bo, out, 1);   // -> out
}

// round 10
// speedup vs baseline: 9.6826x; 1.9226x over previous
#include <cuda_runtime.h>
#include <cuda_fp16.h>
#include <cstdint>

#define BB 2
#define TT 2048
#define DD 1024
#define HH 16
#define DH 64
#define MM (BB*TT)   // 4096

// ---------------- scratch (device globals, no runtime alloc) ----------------
__device__ __align__(16) __half g_Af[3][MM*DD];   // GEMM A fp16 per z (q/k/v; slot 0 reused for attn out)
__device__ __align__(16) __half g_Wf[4][DD*DD];   // W^T fp16 [slot][N][K]
__device__ __align__(16) __half g_Qh[MM*DD];      // Q proj fp16 (pre-scaled 1/32)
__device__ __align__(16) __half g_Kh[MM*DD];      // K proj fp16
__device__ __align__(16) __half g_Vf[MM*DD];      // V proj fp16 [b*T][D]
__device__ __align__(16) __half g_Vt[BB*HH*DH*TT];// V^T fp16 [bh][d][t_compact]
__device__ int g_idx[BB*TT];                      // compacted key -> orig t
__device__ __align__(16) int g_vmask[BB*TT];      // 1 if compacted pos valid
__device__ int g_ntiles[BB];                      // ceil(count/64)

// ---------------- PTX helpers (arch-generic sm_80+) ----------
__device__ __forceinline__ uint32_t smem_u32(const void* p) {
    uint32_t a;
    asm("{ .reg .u64 t; cvta.to.shared.u64 t, %1; cvt.u32.u64 %0, t; }" : "=r"(a) : "l"(p));
    return a;
}
__device__ __forceinline__ void cp16(uint32_t s, const void* g) {
    asm volatile("cp.async.cg.shared.global [%0], [%1], 16;" :: "r"(s), "l"(g));
}
#define CP_COMMIT() asm volatile("cp.async.commit_group;" ::: "memory")
#define CP_WAIT1()  asm volatile("cp.async.wait_group 1;" ::: "memory")
#define CP_WAIT0()  asm volatile("cp.async.wait_group 0;" ::: "memory")

__device__ __forceinline__ void ldsm4(uint32_t& r0, uint32_t& r1, uint32_t& r2,
                                      uint32_t& r3, uint32_t a) {
    asm volatile("ldmatrix.sync.aligned.m8n8.x4.shared.b16 {%0,%1,%2,%3}, [%4];"
                 : "=r"(r0), "=r"(r1), "=r"(r2), "=r"(r3) : "r"(a));
}
__device__ __forceinline__ void ldsm2(uint32_t& r0, uint32_t& r1, uint32_t a) {
    asm volatile("ldmatrix.sync.aligned.m8n8.x2.shared.b16 {%0,%1}, [%2];"
                 : "=r"(r0), "=r"(r1) : "r"(a));
}
__device__ __forceinline__ void mma_fp(float* c, const uint32_t* a, const uint32_t* b) {
    asm volatile(
        "mma.sync.aligned.m16n8k16.row.col.f32.f16.f16.f32 "
        "{%0,%1,%2,%3}, {%4,%5,%6,%7}, {%8,%9}, {%0,%1,%2,%3};"
        : "+f"(c[0]), "+f"(c[1]), "+f"(c[2]), "+f"(c[3])
        : "r"(a[0]), "r"(a[1]), "r"(a[2]), "r"(a[3]), "r"(b[0]), "r"(b[1]));
}
__device__ __forceinline__ uint32_t pack_h2(float a, float b) {
    __half2 h = __floats2half2_rn(a, b);
    return *reinterpret_cast<uint32_t*>(&h);
}

// ---------------------------------------------------------------------------
// convertA3: fp32 q/k/v -> fp16 slots 0/1/2.  grid (MM*DD/1024, 1, 3)
// ---------------------------------------------------------------------------
__global__ __launch_bounds__(256) void convertA3(
    const float* __restrict__ q, const float* __restrict__ k,
    const float* __restrict__ v)
{
    const int z = blockIdx.z;
    const float* src = (z == 0) ? q : (z == 1) ? k : v;
    const int i = (blockIdx.x * 256 + threadIdx.x) * 4;
    float4 x = *reinterpret_cast<const float4*>(src + i);
    uint2 o;
    o.x = pack_h2(x.x, x.y);
    o.y = pack_h2(x.z, x.w);
    *reinterpret_cast<uint2*>(&g_Af[z][i]) = o;
}

// ---------------------------------------------------------------------------
// convertW4: fp32 W[K,N] -> fp16 W^T [N,K], slots 0..3.
// grid (DD/32, DD/32, 4), block (32, 8)
// ---------------------------------------------------------------------------
__global__ __launch_bounds__(256) void convertW4(
    const float* __restrict__ Wq, const float* __restrict__ Wk,
    const float* __restrict__ Wv, const float* __restrict__ Wo)
{
    __shared__ float tile[32][33];
    const int z = blockIdx.z;
    const float* W = (z == 0) ? Wq : (z == 1) ? Wk : (z == 2) ? Wv : Wo;
    const int n0 = blockIdx.x * 32;
    const int k0 = blockIdx.y * 32;
    const int tx = threadIdx.x, ty = threadIdx.y;

    #pragma unroll
    for (int r = 0; r < 4; r++)
        tile[ty + r * 8][tx] = W[(size_t)(k0 + ty + r * 8) * DD + n0 + tx];
    __syncthreads();

    #pragma unroll
    for (int r = 0; r < 4; r++) {
        const int n = ty + r * 8;
        g_Wf[z][(size_t)(n0 + n) * DD + k0 + tx] = __float2half_rn(tile[tx][n]);
    }
}

// ---------------------------------------------------------------------------
// build_idx: deterministic per-batch compaction of valid keys.
// grid = BB, block = 512.
// ---------------------------------------------------------------------------
__global__ __launch_bounds__(512) void build_idx(const int* __restrict__ mask)
{
    __shared__ int wsum[16];
    __shared__ int s_cnt;
    const int b = blockIdx.x, tid = threadIdx.x;
    const int lane = tid & 31, wid = tid >> 5;

    int m[4];
    const int base = b * TT + tid * 4;
    #pragma unroll
    for (int i = 0; i < 4; i++) m[i] = (mask[base + i] != 0) ? 1 : 0;
    const int tot = m[0] + m[1] + m[2] + m[3];

    int scan = tot;
    #pragma unroll
    for (int ofs = 1; ofs < 32; ofs <<= 1) {
        int v = __shfl_up_sync(0xffffffffu, scan, ofs);
        if (lane >= ofs) scan += v;
    }
    if (lane == 31) wsum[wid] = scan;
    __syncthreads();
    if (wid == 0) {
        int v = (lane < 16) ? wsum[lane] : 0;
        #pragma unroll
        for (int ofs = 1; ofs < 16; ofs <<= 1) {
            int t = __shfl_up_sync(0xffffffffu, v, ofs);
            if (lane >= ofs) v += t;
        }
        if (lane < 16) wsum[lane] = v;
        if (lane == 15) s_cnt = v;
    }
    __syncthreads();

    int off = ((wid == 0) ? 0 : wsum[wid - 1]) + scan - tot;
    #pragma unroll
    for (int i = 0; i < 4; i++)
        if (m[i]) g_idx[b * TT + off++] = tid * 4 + i;

    const int cnt = s_cnt;
    #pragma unroll
    for (int i = 0; i < 4; i++) {
        const int j = tid * 4 + i;
        g_vmask[b * TT + j] = (j < cnt) ? 1 : 0;
        if (j >= cnt) g_idx[b * TT + j] = 0;
    }
    if (tid == 0) g_ntiles[b] = (cnt + 63) >> 6;
}

// ---------------------------------------------------------------------------
// convVt: g_Vf fp16 -> COMPACTED V^T fp16 [bh][d][t_compact]
// grid (T/32, D/32, B), block (32, 8)
// ---------------------------------------------------------------------------
__global__ __launch_bounds__(256) void convVt()
{
    __shared__ float tile[32][33];
    const int t0 = blockIdx.x * 32;
    const int b  = blockIdx.z;
    if (t0 >= g_ntiles[b] * 64) return;
    const int d0 = blockIdx.y * 32;
    const int tx = threadIdx.x, ty = threadIdx.y;

    #pragma unroll
    for (int r = 0; r < 4; r++) {
        const int tsrc = g_idx[b * TT + t0 + ty + r * 8];
        tile[ty + r * 8][tx] = __half2float(g_Vf[(size_t)(b * TT + tsrc) * DD + d0 + tx]);
    }
    __syncthreads();

    #pragma unroll
    for (int r = 0; r < 4; r++) {
        const int dl = ty + r * 8;
        const int d  = d0 + dl;
        const int h  = d >> 6, dd = d & 63;
        g_Vt[(size_t)((b * HH + h) * DH + dd) * TT + t0 + tx] =
            __float2half_rn(tile[tx][dl]);
    }
}

// ---------------------------------------------------------------------------
// fp16 HMMA GEMM (single pass): C[M,N] = A[M,K] @ W^T[N,K] + bias
// 128x128 CTA tile, 8 warps (64x32 each), BK=32, cp.async double-buffered.
// final=0: grid (8,32,3) z->q/k/v.  final=1: grid (8,32,1) A slot 0, W slot 3.
// ---------------------------------------------------------------------------
#define TILE_B   10240               // 128 rows * 80 bytes (64B data + 16B pad)
#define BUF_B    (2 * TILE_B)        // A, B
#define GSM_TOT  (2 * BUF_B)         // 40960

__global__ __launch_bounds__(256) void mma_gemm(
    const float* __restrict__ b0, const float* __restrict__ b1,
    const float* __restrict__ b2, float* __restrict__ Cp, int final_)
{
    extern __shared__ char smem[];
    const uint32_t sb = smem_u32(smem);
    const int tid  = threadIdx.x;
    const int wid  = tid >> 5;
    const int lane = tid & 31;
    const int warp_m = wid & 1;
    const int warp_n = wid >> 1;

    const int z    = final_ ? 0 : blockIdx.z;
    const int ws   = final_ ? 3 : z;
    const int mode = final_ ? 3 : z;    // 0->Qh(/32), 1->Kh, 2->Vf, 3->Cp fp32
    const float* bias = (final_ || z == 0) ? b0 : (z == 1 ? b1 : b2);

    const int aBase = blockIdx.y * 128;
    const int bBase = blockIdx.x * 128;
    const __half* srcA = g_Af[z] + (size_t)aBase * DD;
    const __half* srcW = g_Wf[ws] + (size_t)bBase * DD;

    float acc[4][4][4];
    #pragma unroll
    for (int i = 0; i < 4; i++)
        #pragma unroll
        for (int j = 0; j < 4; j++)
            #pragma unroll
            for (int r = 0; r < 4; r++) acc[i][j][r] = 0.f;

    auto load_chunk = [&](int c, int buf) {
        const int c0 = c * 32;
        const uint32_t base = sb + buf * BUF_B;
        #pragma unroll
        for (int it = 0; it < 4; it++) {
            const int idx = tid + it * 256;        // 0..1023
            const int t2  = idx >> 9;              // 0: A, 1: W
            const int rem = idx & 511;
            const int row = rem >> 2;
            const int seg = rem & 3;
            const __half* s = (t2 == 0) ? srcA : srcW;
            cp16(base + t2 * TILE_B + row * 80 + seg * 16,
                 s + (size_t)row * DD + c0 + seg * 8);
        }
    };

    load_chunk(0, 0);
    CP_COMMIT();

    int buf = 0;
    for (int c = 0; c < 32; c++) {
        if (c + 1 < 32) {
            load_chunk(c + 1, buf ^ 1);
            CP_COMMIT();
            CP_WAIT1();
        } else {
            CP_WAIT0();
        }
        __syncthreads();

        const uint32_t sA = sb + buf * BUF_B;
        const uint32_t sB = sA + TILE_B;

        #pragma unroll
        for (int ks = 0; ks < 2; ks++) {
            const int kb = ks * 32;
            uint32_t af[4][4], bf[4][2];

            const int arow = (lane & 15);
            const uint32_t acol = ((lane >> 4) << 4) + kb;
            #pragma unroll
            for (int mt = 0; mt < 4; mt++) {
                const uint32_t ro = (uint32_t)(warp_m * 64 + mt * 16 + arow) * 80 + acol;
                ldsm4(af[mt][0], af[mt][1], af[mt][2], af[mt][3], sA + ro);
            }
            const int brow = (lane & 7);
            const uint32_t bcol = (((lane >> 3) & 1) << 4) + kb;
            #pragma unroll
            for (int nt = 0; nt < 4; nt++) {
                const uint32_t ro = (uint32_t)(warp_n * 32 + nt * 8 + brow) * 80 + bcol;
                ldsm2(bf[nt][0], bf[nt][1], sB + ro);
            }

            #pragma unroll
            for (int mt = 0; mt < 4; mt++)
                #pragma unroll
                for (int nt = 0; nt < 4; nt++)
                    mma_fp(acc[mt][nt], af[mt], bf[nt]);
        }
        __syncthreads();
        buf ^= 1;
    }

    // ---- epilogue ----
    const float qs = (mode == 0) ? 0.03125f : 1.0f;
    #pragma unroll
    for (int mt = 0; mt < 4; mt++) {
        const int row0 = aBase + warp_m * 64 + mt * 16 + (lane >> 2);
        #pragma unroll
        for (int nt = 0; nt < 4; nt++) {
            const int col = bBase + warp_n * 32 + nt * 8 + (lane & 3) * 2;
            const float bb0 = bias[col], bb1 = bias[col + 1];
            float2 v0 = { acc[mt][nt][0] + bb0, acc[mt][nt][1] + bb1 };
            float2 v1 = { acc[mt][nt][2] + bb0, acc[mt][nt][3] + bb1 };
            if (mode == 3) {
                *reinterpret_cast<float2*>(Cp + (size_t)row0 * DD + col) = v0;
                *reinterpret_cast<float2*>(Cp + (size_t)(row0 + 8) * DD + col) = v1;
            } else {
                __half* D = (mode == 0) ? g_Qh : (mode == 1) ? g_Kh : g_Vf;
                *reinterpret_cast<uint32_t*>(D + (size_t)row0 * DD + col) =
                    pack_h2(v0.x * qs, v0.y * qs);
                *reinterpret_cast<uint32_t*>(D + (size_t)(row0 + 8) * DD + col) =
                    pack_h2(v1.x * qs, v1.y * qs);
            }
        }
    }
}

// ---------------------------------------------------------------------------
// Tensor-core flash attention over COMPACTED keys (all fp16 single-pass).
// grid = (T/64 qtiles, B*H), block = 128 (4 warps, 16 q-rows each).
// Output written fp16 directly into g_Af[0] (A of final GEMM).
// ---------------------------------------------------------------------------
#define APB    144            // smem row pitch bytes (64 halves + pad)
#define OFF_K  0
#define OFF_V  9216
#define OFF_MS 18432
#define ABUF   18688
#define ASM_TOT (2*ABUF)      // 37376

__global__ __launch_bounds__(128) void attn_mma()
{
    extern __shared__ char smema[];
    const uint32_t sb = smem_u32(smema);
    const int tid  = threadIdx.x;
    const int lane = tid & 31;
    const int w    = tid >> 5;
    const int bh   = blockIdx.y;
    const int b    = bh >> 4, h = bh & 15;
    const int q0   = blockIdx.x * 64;
    const int c0   = (lane & 3) * 2;
    const float NEGINF = -__int_as_float(0x7f800000);

    const int ntk = g_ntiles[b];
    const int* idxb = g_idx + b * TT;

    // preload Q A-frags (fp16, pre-scaled 1/32)
    uint32_t qa[4][4];
    {
        const int r = q0 + w * 16 + (lane >> 2);
        const __half* Qb = g_Qh + (size_t)(b * TT + r) * DD + h * 64;
        #pragma unroll
        for (int t = 0; t < 4; t++) {
            qa[t][0] = *reinterpret_cast<const uint32_t*>(Qb + t * 16 + c0);
            qa[t][1] = *reinterpret_cast<const uint32_t*>(Qb + 8 * DD + t * 16 + c0);
            qa[t][2] = *reinterpret_cast<const uint32_t*>(Qb + t * 16 + 8 + c0);
            qa[t][3] = *reinterpret_cast<const uint32_t*>(Qb + 8 * DD + t * 16 + 8 + c0);
        }
    }

    auto load_tiles = [&](int kt, int bufsel) {
        const uint32_t base = sb + bufsel * ABUF;
        const int s0 = kt * 64;
        #pragma unroll
        for (int it = 0; it < 4; it++) {
            const int idx = tid + it * 128;       // 0..511
            const int row = idx >> 3, seg = idx & 7;
            const int src = idxb[s0 + row];       // gather K through compaction idx
            cp16(base + OFF_K + row * APB + seg * 16,
                 g_Kh + (size_t)(b * TT + src) * DD + h * 64 + seg * 8);
            cp16(base + OFF_V + row * APB + seg * 16,
                 g_Vt + (size_t)(bh * DH + row) * TT + s0 + seg * 8);
        }
        if (tid < 16) cp16(base + OFF_MS + tid * 16, g_vmask + b * TT + s0 + tid * 4);
    };

    float o[8][4];
    #pragma unroll
    for (int n = 0; n < 8; n++)
        #pragma unroll
        for (int r = 0; r < 4; r++) o[n][r] = 0.f;
    float m0 = -1e30f, m1 = -1e30f, l0 = 0.f, l1 = 0.f;

    load_tiles(0, 0);
    CP_COMMIT();

    int buf = 0;
    for (int kt = 0; kt < ntk; kt++) {
        if (kt + 1 < ntk) {
            load_tiles(kt + 1, buf ^ 1);
            CP_COMMIT();
            CP_WAIT1();
        } else {
            CP_WAIT0();
        }
        __syncthreads();
        const uint32_t base = sb + buf * ABUF;

        // ---- S = Q K^T (fp16, fp32 accum) ----
        float sf[8][4];
        #pragma unroll
        for (int j = 0; j < 8; j++) {
            sf[j][0] = sf[j][1] = sf[j][2] = sf[j][3] = 0.f;
            uint32_t kA[4], kB[4];
            const uint32_t ka = base + OFF_K + (j * 8 + (lane & 7)) * APB
                              + ((lane >> 3) & 3) * 16;
            ldsm4(kA[0], kA[1], kA[2], kA[3], ka);
            ldsm4(kB[0], kB[1], kB[2], kB[3], ka + 64);
            mma_fp(sf[j], qa[0], &kA[0]);
            mma_fp(sf[j], qa[1], &kA[2]);
            mma_fp(sf[j], qa[2], &kB[0]);
            mma_fp(sf[j], qa[3], &kB[2]);
        }

        // ---- mask padded tail + online softmax ----
        float p[8][4];
        float mx0 = NEGINF, mx1 = NEGINF;
        #pragma unroll
        for (int j = 0; j < 8; j++) {
            const int2 mk = *reinterpret_cast<const int2*>(
                smema + buf * ABUF + OFF_MS + (j * 8 + c0) * 4);
            sf[j][0] = mk.x ? sf[j][0] : NEGINF;
            sf[j][1] = mk.y ? sf[j][1] : NEGINF;
            sf[j][2] = mk.x ? sf[j][2] : NEGINF;
            sf[j][3] = mk.y ? sf[j][3] : NEGINF;
            mx0 = fmaxf(mx0, fmaxf(sf[j][0], sf[j][1]));
            mx1 = fmaxf(mx1, fmaxf(sf[j][2], sf[j][3]));
        }
        mx0 = fmaxf(mx0, __shfl_xor_sync(0xffffffffu, mx0, 1));
        mx0 = fmaxf(mx0, __shfl_xor_sync(0xffffffffu, mx0, 2));
        mx1 = fmaxf(mx1, __shfl_xor_sync(0xffffffffu, mx1, 1));
        mx1 = fmaxf(mx1, __shfl_xor_sync(0xffffffffu, mx1, 2));

        const float mn0 = fmaxf(m0, mx0), mn1 = fmaxf(m1, mx1);
        const float sc0 = __expf(m0 - mn0), sc1 = __expf(m1 - mn1);
        float sum0 = 0.f, sum1 = 0.f;
        #pragma unroll
        for (int j = 0; j < 8; j++) {
            p[j][0] = __expf(sf[j][0] - mn0);
            p[j][1] = __expf(sf[j][1] - mn0);
            p[j][2] = __expf(sf[j][2] - mn1);
            p[j][3] = __expf(sf[j][3] - mn1);
            sum0 += p[j][0] + p[j][1];
            sum1 += p[j][2] + p[j][3];
        }
        sum0 += __shfl_xor_sync(0xffffffffu, sum0, 1);
        sum0 += __shfl_xor_sync(0xffffffffu, sum0, 2);
        sum1 += __shfl_xor_sync(0xffffffffu, sum1, 1);
        sum1 += __shfl_xor_sync(0xffffffffu, sum1, 2);
        l0 = l0 * sc0 + sum0;
        l1 = l1 * sc1 + sum1;
        m0 = mn0;
        m1 = mn1;
        #pragma unroll
        for (int n = 0; n < 8; n++) {
            o[n][0] *= sc0; o[n][1] *= sc0;
            o[n][2] *= sc1; o[n][3] *= sc1;
        }

        // ---- pack P -> fp16 A-frags ----
        uint32_t pa[4][4];
        #pragma unroll
        for (int t = 0; t < 4; t++) {
            pa[t][0] = pack_h2(p[2*t][0],   p[2*t][1]);
            pa[t][1] = pack_h2(p[2*t][2],   p[2*t][3]);
            pa[t][2] = pack_h2(p[2*t+1][0], p[2*t+1][1]);
            pa[t][3] = pack_h2(p[2*t+1][2], p[2*t+1][3]);
        }

        // ---- O += P V  (fp16 single pass; B = V^T tiles) ----
        #pragma unroll
        for (int n = 0; n < 8; n++) {
            uint32_t vA[4], vB[4];
            const uint32_t va = base + OFF_V + (n * 8 + (lane & 7)) * APB
                              + ((lane >> 3) & 3) * 16;
            ldsm4(vA[0], vA[1], vA[2], vA[3], va);
            ldsm4(vB[0], vB[1], vB[2], vB[3], va + 64);
            mma_fp(o[n], pa[0], &vA[0]);
            mma_fp(o[n], pa[1], &vA[2]);
            mma_fp(o[n], pa[2], &vB[0]);
            mma_fp(o[n], pa[3], &vB[2]);
        }

        __syncthreads();
        buf ^= 1;
    }

    // ---- epilogue: o/l -> fp16 directly into final-GEMM A slot 0 ----
    const float i0 = 1.f / l0, i1 = 1.f / l1;
    const int r0 = q0 + w * 16 + (lane >> 2);
    #pragma unroll
    for (int n = 0; n < 8; n++) {
        const size_t a0 = (size_t)(b * TT + r0) * DD + h * 64 + n * 8 + c0;
        const size_t a1 = a0 + 8 * DD;
        *reinterpret_cast<uint32_t*>(&g_Af[0][a0]) = pack_h2(o[n][0] * i0, o[n][1] * i0);
        *reinterpret_cast<uint32_t*>(&g_Af[0][a1]) = pack_h2(o[n][2] * i1, o[n][3] * i1);
    }
}

// ---------------------------------------------------------------------------
// Launch
// ---------------------------------------------------------------------------
extern "C" void kernel_launch(void* const* d_in, const int* in_sizes, int n_in,
                              void* d_out, int out_size)
{
    const float* q    = (const float*)d_in[0];
    const float* k    = (const float*)d_in[1];
    const float* v    = (const float*)d_in[2];
    const int*   mask = (const int*)  d_in[3];
    const float* Wq   = (const float*)d_in[4];
    const float* bq   = (const float*)d_in[5];
    const float* Wk   = (const float*)d_in[6];
    const float* bk   = (const float*)d_in[7];
    const float* Wv   = (const float*)d_in[8];
    const float* bv   = (const float*)d_in[9];
    const float* Wo   = (const float*)d_in[10];
    const float* bo   = (const float*)d_in[11];
    float* out = (float*)d_out;

    cudaFuncSetAttribute(mma_gemm, cudaFuncAttributeMaxDynamicSharedMemorySize, GSM_TOT);
    cudaFuncSetAttribute(attn_mma, cudaFuncAttributeMaxDynamicSharedMemorySize, ASM_TOT);

    const dim3 cgrid(MM * DD / 4 / 256, 1, 3);
    const dim3 wgrid(DD / 32, DD / 32, 4);
    const dim3 wblk(32, 8);
    const dim3 pgrid(DD / 128, MM / 128, 3);   // batched projections
    const dim3 fgrid(DD / 128, MM / 128, 1);   // final GEMM
    const dim3 vgrid(TT / 32, DD / 32, BB);
    const dim3 agrid(TT / 64, BB * HH);

    convertW4<<<wgrid, wblk>>>(Wq, Wk, Wv, Wo);                // W^T fp16
    convertA3<<<cgrid, 256>>>(q, k, v);                        // A fp16
    build_idx<<<BB, 512>>>(mask);                              // key compaction

    mma_gemm<<<pgrid, 256, GSM_TOT>>>(bq, bk, bv, nullptr, 0); // Qh, Kh, Vf

    convVt<<<vgrid, wblk>>>();                                 // compacted V^T

    attn_mma<<<agrid, 128, ASM_TOT>>>();                       // -> g_Af[0]

    mma_gemm<<<fgrid, 256, GSM_TOT>>>(bo, bo, bo, out, 1);     // -> out
}

// round 11
// speedup vs baseline: 10.9099x; 1.1267x over previous
#include <cuda_runtime.h>
#include <cuda_fp16.h>
#include <cstdint>

#define BB 2
#define TT 2048
#define DD 1024
#define HH 16
#define DH 64
#define MM (BB*TT)   // 4096

// ---------------- scratch (device globals, no runtime alloc) ----------------
__device__ __align__(16) __half g_Af[3][MM*DD];   // GEMM A fp16 per z (slot 0 reused for attn out)
__device__ __align__(16) __half g_Wf[4][DD*DD];   // W^T fp16 [slot][N][K]
__device__ __align__(16) __half g_Qh[MM*DD];      // Q proj fp16 (pre-scaled 1/32)
__device__ __align__(16) __half g_Kh[MM*DD];      // K proj fp16
__device__ __align__(16) __half g_Vf[MM*DD];      // V proj fp16 [b*T][D]
__device__ int g_idx[BB*TT];                      // compacted key -> orig t
__device__ __align__(16) int g_vmask[BB*TT];      // 1 if compacted pos valid
__device__ int g_ntiles[BB];                      // ceil(count/64)

// ---------------- PTX helpers (arch-generic sm_80+) ----------
__device__ __forceinline__ uint32_t smem_u32(const void* p) {
    uint32_t a;
    asm("{ .reg .u64 t; cvta.to.shared.u64 t, %1; cvt.u32.u64 %0, t; }" : "=r"(a) : "l"(p));
    return a;
}
__device__ __forceinline__ void cp16(uint32_t s, const void* g) {
    asm volatile("cp.async.cg.shared.global [%0], [%1], 16;" :: "r"(s), "l"(g));
}
#define CP_COMMIT() asm volatile("cp.async.commit_group;" ::: "memory")
#define CP_WAIT1()  asm volatile("cp.async.wait_group 1;" ::: "memory")
#define CP_WAIT0()  asm volatile("cp.async.wait_group 0;" ::: "memory")

__device__ __forceinline__ void ldsm4(uint32_t& r0, uint32_t& r1, uint32_t& r2,
                                      uint32_t& r3, uint32_t a) {
    asm volatile("ldmatrix.sync.aligned.m8n8.x4.shared.b16 {%0,%1,%2,%3}, [%4];"
                 : "=r"(r0), "=r"(r1), "=r"(r2), "=r"(r3) : "r"(a));
}
__device__ __forceinline__ void ldsm4t(uint32_t& r0, uint32_t& r1, uint32_t& r2,
                                       uint32_t& r3, uint32_t a) {
    asm volatile("ldmatrix.sync.aligned.m8n8.x4.trans.shared.b16 {%0,%1,%2,%3}, [%4];"
                 : "=r"(r0), "=r"(r1), "=r"(r2), "=r"(r3) : "r"(a));
}
__device__ __forceinline__ void ldsm2(uint32_t& r0, uint32_t& r1, uint32_t a) {
    asm volatile("ldmatrix.sync.aligned.m8n8.x2.shared.b16 {%0,%1}, [%2];"
                 : "=r"(r0), "=r"(r1) : "r"(a));
}
__device__ __forceinline__ void mma_fp(float* c, const uint32_t* a, const uint32_t* b) {
    asm volatile(
        "mma.sync.aligned.m16n8k16.row.col.f32.f16.f16.f32 "
        "{%0,%1,%2,%3}, {%4,%5,%6,%7}, {%8,%9}, {%0,%1,%2,%3};"
        : "+f"(c[0]), "+f"(c[1]), "+f"(c[2]), "+f"(c[3])
        : "r"(a[0]), "r"(a[1]), "r"(a[2]), "r"(a[3]), "r"(b[0]), "r"(b[1]));
}
__device__ __forceinline__ uint32_t pack_h2(float a, float b) {
    __half2 h = __floats2half2_rn(a, b);
    return *reinterpret_cast<uint32_t*>(&h);
}

// ---------------------------------------------------------------------------
// convertA3: fp32 q/k/v -> fp16 slots 0/1/2.  grid (MM*DD/1024, 1, 3)
// ---------------------------------------------------------------------------
__global__ __launch_bounds__(256) void convertA3(
    const float* __restrict__ q, const float* __restrict__ k,
    const float* __restrict__ v)
{
    const int z = blockIdx.z;
    const float* src = (z == 0) ? q : (z == 1) ? k : v;
    const int i = (blockIdx.x * 256 + threadIdx.x) * 4;
    float4 x = *reinterpret_cast<const float4*>(src + i);
    uint2 o;
    o.x = pack_h2(x.x, x.y);
    o.y = pack_h2(x.z, x.w);
    *reinterpret_cast<uint2*>(&g_Af[z][i]) = o;
}

// ---------------------------------------------------------------------------
// convertW4: fp32 W[K,N] -> fp16 W^T [N,K], slots 0..3.
// grid (DD/32, DD/32, 4), block (32, 8)
// ---------------------------------------------------------------------------
__global__ __launch_bounds__(256) void convertW4(
    const float* __restrict__ Wq, const float* __restrict__ Wk,
    const float* __restrict__ Wv, const float* __restrict__ Wo)
{
    __shared__ float tile[32][33];
    const int z = blockIdx.z;
    const float* W = (z == 0) ? Wq : (z == 1) ? Wk : (z == 2) ? Wv : Wo;
    const int n0 = blockIdx.x * 32;
    const int k0 = blockIdx.y * 32;
    const int tx = threadIdx.x, ty = threadIdx.y;

    #pragma unroll
    for (int r = 0; r < 4; r++)
        tile[ty + r * 8][tx] = W[(size_t)(k0 + ty + r * 8) * DD + n0 + tx];
    __syncthreads();

    #pragma unroll
    for (int r = 0; r < 4; r++) {
        const int n = ty + r * 8;
        g_Wf[z][(size_t)(n0 + n) * DD + k0 + tx] = __float2half_rn(tile[tx][n]);
    }
}

// ---------------------------------------------------------------------------
// build_idx: deterministic per-batch compaction of valid keys.
// grid = BB, block = 512.
// ---------------------------------------------------------------------------
__global__ __launch_bounds__(512) void build_idx(const int* __restrict__ mask)
{
    __shared__ int wsum[16];
    __shared__ int s_cnt;
    const int b = blockIdx.x, tid = threadIdx.x;
    const int lane = tid & 31, wid = tid >> 5;

    int m[4];
    const int base = b * TT + tid * 4;
    #pragma unroll
    for (int i = 0; i < 4; i++) m[i] = (mask[base + i] != 0) ? 1 : 0;
    const int tot = m[0] + m[1] + m[2] + m[3];

    int scan = tot;
    #pragma unroll
    for (int ofs = 1; ofs < 32; ofs <<= 1) {
        int v = __shfl_up_sync(0xffffffffu, scan, ofs);
        if (lane >= ofs) scan += v;
    }
    if (lane == 31) wsum[wid] = scan;
    __syncthreads();
    if (wid == 0) {
        int v = (lane < 16) ? wsum[lane] : 0;
        #pragma unroll
        for (int ofs = 1; ofs < 16; ofs <<= 1) {
            int t = __shfl_up_sync(0xffffffffu, v, ofs);
            if (lane >= ofs) v += t;
        }
        if (lane < 16) wsum[lane] = v;
        if (lane == 15) s_cnt = v;
    }
    __syncthreads();

    int off = ((wid == 0) ? 0 : wsum[wid - 1]) + scan - tot;
    #pragma unroll
    for (int i = 0; i < 4; i++)
        if (m[i]) g_idx[b * TT + off++] = tid * 4 + i;

    const int cnt = s_cnt;
    #pragma unroll
    for (int i = 0; i < 4; i++) {
        const int j = tid * 4 + i;
        g_vmask[b * TT + j] = (j < cnt) ? 1 : 0;
        if (j >= cnt) g_idx[b * TT + j] = 0;
    }
    if (tid == 0) g_ntiles[b] = (cnt + 63) >> 6;
}

// ---------------------------------------------------------------------------
// fp16 HMMA GEMM: C[M,N] = A[M,K] @ W^T[N,K] + bias
// 128x128 CTA tile, 8 warps (64x32 each), BK=32, 3-stage cp.async pipeline
// (single __syncthreads per chunk).
// final=0: grid (8,32,3) z->q/k/v.  final=1: grid (8,32,1) A slot 0, W slot 3.
// ---------------------------------------------------------------------------
#define TILE_B   10240               // 128 rows * 80 bytes (64B data + 16B pad)
#define BUF_B    (2 * TILE_B)        // A, B
#define GSM_TOT  (3 * BUF_B)         // 61440, 3 stages

__global__ __launch_bounds__(256, 2) void mma_gemm(
    const float* __restrict__ b0, const float* __restrict__ b1,
    const float* __restrict__ b2, float* __restrict__ Cp, int final_)
{
    extern __shared__ char smem[];
    const uint32_t sb = smem_u32(smem);
    const int tid  = threadIdx.x;
    const int wid  = tid >> 5;
    const int lane = tid & 31;
    const int warp_m = wid & 1;
    const int warp_n = wid >> 1;

    const int z    = final_ ? 0 : blockIdx.z;
    const int ws   = final_ ? 3 : z;
    const int mode = final_ ? 3 : z;    // 0->Qh(/32), 1->Kh, 2->Vf, 3->Cp fp32
    const float* bias = (final_ || z == 0) ? b0 : (z == 1 ? b1 : b2);

    const int aBase = blockIdx.y * 128;
    const int bBase = blockIdx.x * 128;
    const __half* srcA = g_Af[z] + (size_t)aBase * DD;
    const __half* srcW = g_Wf[ws] + (size_t)bBase * DD;

    float acc[4][4][4];
    #pragma unroll
    for (int i = 0; i < 4; i++)
        #pragma unroll
        for (int j = 0; j < 4; j++)
            #pragma unroll
            for (int r = 0; r < 4; r++) acc[i][j][r] = 0.f;

    auto load_chunk = [&](int c, int buf) {
        const int c0 = c * 32;
        const uint32_t base = sb + buf * BUF_B;
        #pragma unroll
        for (int it = 0; it < 4; it++) {
            const int idx = tid + it * 256;        // 0..1023
            const int t2  = idx >> 9;              // 0: A, 1: W
            const int rem = idx & 511;
            const int row = rem >> 2;
            const int seg = rem & 3;
            const __half* s = (t2 == 0) ? srcA : srcW;
            cp16(base + t2 * TILE_B + row * 80 + seg * 16,
                 s + (size_t)row * DD + c0 + seg * 8);
        }
    };

    load_chunk(0, 0); CP_COMMIT();
    load_chunk(1, 1); CP_COMMIT();

    int cb = 0, lb = 2;
    for (int c = 0; c < 32; c++) {
        if (c < 31) { CP_WAIT1(); } else { CP_WAIT0(); }
        __syncthreads();                  // all warps done with buffer lb, data for c visible

        if (c + 2 < 32) {
            load_chunk(c + 2, lb);
            CP_COMMIT();
        }

        const uint32_t sA = sb + cb * BUF_B;
        const uint32_t sB = sA + TILE_B;

        #pragma unroll
        for (int ks = 0; ks < 2; ks++) {
            const int kb = ks * 32;
            uint32_t af[4][4], bf[4][2];

            const int arow = (lane & 15);
            const uint32_t acol = ((lane >> 4) << 4) + kb;
            #pragma unroll
            for (int mt = 0; mt < 4; mt++) {
                const uint32_t ro = (uint32_t)(warp_m * 64 + mt * 16 + arow) * 80 + acol;
                ldsm4(af[mt][0], af[mt][1], af[mt][2], af[mt][3], sA + ro);
            }
            const int brow = (lane & 7);
            const uint32_t bcol = (((lane >> 3) & 1) << 4) + kb;
            #pragma unroll
            for (int nt = 0; nt < 4; nt++) {
                const uint32_t ro = (uint32_t)(warp_n * 32 + nt * 8 + brow) * 80 + bcol;
                ldsm2(bf[nt][0], bf[nt][1], sB + ro);
            }

            #pragma unroll
            for (int mt = 0; mt < 4; mt++)
                #pragma unroll
                for (int nt = 0; nt < 4; nt++)
                    mma_fp(acc[mt][nt], af[mt], bf[nt]);
        }

        cb = (cb == 2) ? 0 : cb + 1;
        lb = (lb == 2) ? 0 : lb + 1;
    }

    // ---- epilogue ----
    const float qs = (mode == 0) ? 0.03125f : 1.0f;
    #pragma unroll
    for (int mt = 0; mt < 4; mt++) {
        const int row0 = aBase + warp_m * 64 + mt * 16 + (lane >> 2);
        #pragma unroll
        for (int nt = 0; nt < 4; nt++) {
            const int col = bBase + warp_n * 32 + nt * 8 + (lane & 3) * 2;
            const float bb0 = bias[col], bb1 = bias[col + 1];
            float2 v0 = { acc[mt][nt][0] + bb0, acc[mt][nt][1] + bb1 };
            float2 v1 = { acc[mt][nt][2] + bb0, acc[mt][nt][3] + bb1 };
            if (mode == 3) {
                *reinterpret_cast<float2*>(Cp + (size_t)row0 * DD + col) = v0;
                *reinterpret_cast<float2*>(Cp + (size_t)(row0 + 8) * DD + col) = v1;
            } else {
                __half* D = (mode == 0) ? g_Qh : (mode == 1) ? g_Kh : g_Vf;
                *reinterpret_cast<uint32_t*>(D + (size_t)row0 * DD + col) =
                    pack_h2(v0.x * qs, v0.y * qs);
                *reinterpret_cast<uint32_t*>(D + (size_t)(row0 + 8) * DD + col) =
                    pack_h2(v1.x * qs, v1.y * qs);
            }
        }
    }
}

// ---------------------------------------------------------------------------
// Tensor-core flash attention over COMPACTED keys (fp16, 3-stage pipeline).
// grid = (T/64 qtiles, B*H), block = 128 (4 warps, 16 q-rows each).
// V loaded ROW-major (gathered via idx, same as K) and transposed at
// ldmatrix time (.trans) for the P*V B operand — no V^T pre-pass needed.
// Output written fp16 directly into g_Af[0] (A of final GEMM).
// ---------------------------------------------------------------------------
#define APB    144            // smem row pitch bytes (64 halves + pad)
#define OFF_K  0
#define OFF_V  9216
#define OFF_MS 18432
#define ABUF   18688
#define ASM_TOT (3*ABUF)      // 56064, 3 stages

__global__ __launch_bounds__(128) void attn_mma()
{
    extern __shared__ char smema[];
    const uint32_t sb = smem_u32(smema);
    const int tid  = threadIdx.x;
    const int lane = tid & 31;
    const int w    = tid >> 5;
    const int bh   = blockIdx.y;
    const int b    = bh >> 4, h = bh & 15;
    const int q0   = blockIdx.x * 64;
    const int c0   = (lane & 3) * 2;
    const float NEGINF = -__int_as_float(0x7f800000);

    const int ntk = g_ntiles[b];
    const int* idxb = g_idx + b * TT;

    // preload Q A-frags (fp16, pre-scaled 1/32)
    uint32_t qa[4][4];
    {
        const int r = q0 + w * 16 + (lane >> 2);
        const __half* Qb = g_Qh + (size_t)(b * TT + r) * DD + h * 64;
        #pragma unroll
        for (int t = 0; t < 4; t++) {
            qa[t][0] = *reinterpret_cast<const uint32_t*>(Qb + t * 16 + c0);
            qa[t][1] = *reinterpret_cast<const uint32_t*>(Qb + 8 * DD + t * 16 + c0);
            qa[t][2] = *reinterpret_cast<const uint32_t*>(Qb + t * 16 + 8 + c0);
            qa[t][3] = *reinterpret_cast<const uint32_t*>(Qb + 8 * DD + t * 16 + 8 + c0);
        }
    }

    auto load_tiles = [&](int kt, int bufsel) {
        const uint32_t base = sb + bufsel * ABUF;
        const int s0 = kt * 64;
        #pragma unroll
        for (int it = 0; it < 4; it++) {
            const int idx = tid + it * 128;       // 0..511
            const int row = idx >> 3, seg = idx & 7;
            const int src = idxb[s0 + row];       // gather through compaction idx
            cp16(base + OFF_K + row * APB + seg * 16,
                 g_Kh + (size_t)(b * TT + src) * DD + h * 64 + seg * 8);
            cp16(base + OFF_V + row * APB + seg * 16,
                 g_Vf + (size_t)(b * TT + src) * DD + h * 64 + seg * 8);
        }
        if (tid < 16) cp16(base + OFF_MS + tid * 16, g_vmask + b * TT + s0 + tid * 4);
    };

    float o[8][4];
    #pragma unroll
    for (int n = 0; n < 8; n++)
        #pragma unroll
        for (int r = 0; r < 4; r++) o[n][r] = 0.f;
    float m0 = -1e30f, m1 = -1e30f, l0 = 0.f, l1 = 0.f;

    load_tiles(0, 0); CP_COMMIT();
    if (ntk > 1) { load_tiles(1, 1); CP_COMMIT(); }

    int cb = 0, lb = 2;
    for (int kt = 0; kt < ntk; kt++) {
        if (kt < ntk - 1) { CP_WAIT1(); } else { CP_WAIT0(); }
        __syncthreads();

        if (kt + 2 < ntk) {
            load_tiles(kt + 2, lb);
            CP_COMMIT();
        }

        const uint32_t base = sb + cb * ABUF;

        // ---- S = Q K^T (fp16, fp32 accum) ----
        float sf[8][4];
        #pragma unroll
        for (int j = 0; j < 8; j++) {
            sf[j][0] = sf[j][1] = sf[j][2] = sf[j][3] = 0.f;
            uint32_t kA[4], kB[4];
            const uint32_t ka = base + OFF_K + (j * 8 + (lane & 7)) * APB
                              + ((lane >> 3) & 3) * 16;
            ldsm4(kA[0], kA[1], kA[2], kA[3], ka);
            ldsm4(kB[0], kB[1], kB[2], kB[3], ka + 64);
            mma_fp(sf[j], qa[0], &kA[0]);
            mma_fp(sf[j], qa[1], &kA[2]);
            mma_fp(sf[j], qa[2], &kB[0]);
            mma_fp(sf[j], qa[3], &kB[2]);
        }

        // ---- mask (incl. padded tail) + online softmax ----
        float p[8][4];
        float mx0 = NEGINF, mx1 = NEGINF;
        #pragma unroll
        for (int j = 0; j < 8; j++) {
            const int2 mk = *reinterpret_cast<const int2*>(
                smema + cb * ABUF + OFF_MS + (j * 8 + c0) * 4);
            sf[j][0] = mk.x ? sf[j][0] : NEGINF;
            sf[j][1] = mk.y ? sf[j][1] : NEGINF;
            sf[j][2] = mk.x ? sf[j][2] : NEGINF;
            sf[j][3] = mk.y ? sf[j][3] : NEGINF;
            mx0 = fmaxf(mx0, fmaxf(sf[j][0], sf[j][1]));
            mx1 = fmaxf(mx1, fmaxf(sf[j][2], sf[j][3]));
        }
        mx0 = fmaxf(mx0, __shfl_xor_sync(0xffffffffu, mx0, 1));
        mx0 = fmaxf(mx0, __shfl_xor_sync(0xffffffffu, mx0, 2));
        mx1 = fmaxf(mx1, __shfl_xor_sync(0xffffffffu, mx1, 1));
        mx1 = fmaxf(mx1, __shfl_xor_sync(0xffffffffu, mx1, 2));

        const float mn0 = fmaxf(m0, mx0), mn1 = fmaxf(m1, mx1);
        const float sc0 = __expf(m0 - mn0), sc1 = __expf(m1 - mn1);
        float sum0 = 0.f, sum1 = 0.f;
        #pragma unroll
        for (int j = 0; j < 8; j++) {
            p[j][0] = __expf(sf[j][0] - mn0);
            p[j][1] = __expf(sf[j][1] - mn0);
            p[j][2] = __expf(sf[j][2] - mn1);
            p[j][3] = __expf(sf[j][3] - mn1);
            sum0 += p[j][0] + p[j][1];
            sum1 += p[j][2] + p[j][3];
        }
        sum0 += __shfl_xor_sync(0xffffffffu, sum0, 1);
        sum0 += __shfl_xor_sync(0xffffffffu, sum0, 2);
        sum1 += __shfl_xor_sync(0xffffffffu, sum1, 1);
        sum1 += __shfl_xor_sync(0xffffffffu, sum1, 2);
        l0 = l0 * sc0 + sum0;
        l1 = l1 * sc1 + sum1;
        m0 = mn0;
        m1 = mn1;
        #pragma unroll
        for (int n = 0; n < 8; n++) {
            o[n][0] *= sc0; o[n][1] *= sc0;
            o[n][2] *= sc1; o[n][3] *= sc1;
        }

        // ---- pack P -> fp16 A-frags (pa[t] covers keys 16t..16t+15) ----
        uint32_t pa[4][4];
        #pragma unroll
        for (int t = 0; t < 4; t++) {
            pa[t][0] = pack_h2(p[2*t][0],   p[2*t][1]);
            pa[t][1] = pack_h2(p[2*t][2],   p[2*t][3]);
            pa[t][2] = pack_h2(p[2*t+1][0], p[2*t+1][1]);
            pa[t][3] = pack_h2(p[2*t+1][2], p[2*t+1][3]);
        }

        // ---- O += P V  (V row-major in smem, transposed by ldsm.trans) ----
        #pragma unroll
        for (int n = 0; n < 8; n++) {
            uint32_t vA[4], vB[4];
            // trans tiles: rows = keys (lane -> key lane), cols = d block n*8
            const uint32_t va = base + OFF_V + (uint32_t)lane * APB + n * 16;
            ldsm4t(vA[0], vA[1], vA[2], vA[3], va);              // keys 0..31
            ldsm4t(vB[0], vB[1], vB[2], vB[3], va + 32 * APB);   // keys 32..63
            mma_fp(o[n], pa[0], &vA[0]);
            mma_fp(o[n], pa[1], &vA[2]);
            mma_fp(o[n], pa[2], &vB[0]);
            mma_fp(o[n], pa[3], &vB[2]);
        }

        cb = (cb == 2) ? 0 : cb + 1;
        lb = (lb == 2) ? 0 : lb + 1;
    }

    // ---- epilogue: o/l -> fp16 directly into final-GEMM A slot 0 ----
    const float i0 = 1.f / l0, i1 = 1.f / l1;
    const int r0 = q0 + w * 16 + (lane >> 2);
    #pragma unroll
    for (int n = 0; n < 8; n++) {
        const size_t a0 = (size_t)(b * TT + r0) * DD + h * 64 + n * 8 + c0;
        const size_t a1 = a0 + 8 * DD;
        *reinterpret_cast<uint32_t*>(&g_Af[0][a0]) = pack_h2(o[n][0] * i0, o[n][1] * i0);
        *reinterpret_cast<uint32_t*>(&g_Af[0][a1]) = pack_h2(o[n][2] * i1, o[n][3] * i1);
    }
}

// ---------------------------------------------------------------------------
// Launch
// ---------------------------------------------------------------------------
extern "C" void kernel_launch(void* const* d_in, const int* in_sizes, int n_in,
                              void* d_out, int out_size)
{
    const float* q    = (const float*)d_in[0];
    const float* k    = (const float*)d_in[1];
    const float* v    = (const float*)d_in[2];
    const int*   mask = (const int*)  d_in[3];
    const float* Wq   = (const float*)d_in[4];
    const float* bq   = (const float*)d_in[5];
    const float* Wk   = (const float*)d_in[6];
    const float* bk   = (const float*)d_in[7];
    const float* Wv   = (const float*)d_in[8];
    const float* bv   = (const float*)d_in[9];
    const float* Wo   = (const float*)d_in[10];
    const float* bo   = (const float*)d_in[11];
    float* out = (float*)d_out;

    cudaFuncSetAttribute(mma_gemm, cudaFuncAttributeMaxDynamicSharedMemorySize, GSM_TOT);
    cudaFuncSetAttribute(attn_mma, cudaFuncAttributeMaxDynamicSharedMemorySize, ASM_TOT);

    const dim3 cgrid(MM * DD / 4 / 256, 1, 3);
    const dim3 wgrid(DD / 32, DD / 32, 4);
    const dim3 wblk(32, 8);
    const dim3 pgrid(DD / 128, MM / 128, 3);   // batched projections
    const dim3 fgrid(DD / 128, MM / 128, 1);   // final GEMM
    const dim3 agrid(TT / 64, BB * HH);

    convertW4<<<wgrid, wblk>>>(Wq, Wk, Wv, Wo);                // W^T fp16
    convertA3<<<cgrid, 256>>>(q, k, v);                        // A fp16
    build_idx<<<BB, 512>>>(mask);                              // key compaction

    mma_gemm<<<pgrid, 256, GSM_TOT>>>(bq, bk, bv, nullptr, 0); // Qh, Kh, Vf

    attn_mma<<<agrid, 128, ASM_TOT>>>();                       // -> g_Af[0]

    mma_gemm<<<fgrid, 256, GSM_TOT>>>(bo, bo, bo, out, 1);     // -> out
}

// round 12
// speedup vs baseline: 12.9310x; 1.1853x over previous
#include <cuda_runtime.h>
#include <cuda_fp16.h>
#include <cstdint>

#define BB 2
#define TT 2048
#define DD 1024
#define HH 16
#define DH 64
#define MM (BB*TT)   // 4096

// ---------------- scratch (device globals, no runtime alloc) ----------------
__device__ __align__(16) __half g_Af[3][MM*DD];   // GEMM A fp16 per z (slot 0 reused for attn out)
__device__ __align__(16) __half g_Wf[4][DD*DD];   // W^T fp16 [slot][N][K]
__device__ __align__(16) __half g_Qh[MM*DD];      // Q proj fp16 (pre-scaled 1/32)
__device__ __align__(16) __half g_Kh[MM*DD];      // K proj fp16 (COMPACTED rows)
__device__ __align__(16) __half g_Vf[MM*DD];      // V proj fp16 (COMPACTED rows)
__device__ int g_idx[BB*TT];                      // compacted key -> orig t
__device__ __align__(16) int g_vmask[BB*TT];      // 1 if compacted pos valid
__device__ int g_ntiles[BB];                      // ceil(count/64)

// ---------------- PTX helpers (arch-generic sm_80+) ----------
__device__ __forceinline__ uint32_t smem_u32(const void* p) {
    uint32_t a;
    asm("{ .reg .u64 t; cvta.to.shared.u64 t, %1; cvt.u32.u64 %0, t; }" : "=r"(a) : "l"(p));
    return a;
}
__device__ __forceinline__ void cp16(uint32_t s, const void* g) {
    asm volatile("cp.async.cg.shared.global [%0], [%1], 16;" :: "r"(s), "l"(g));
}
#define CP_COMMIT() asm volatile("cp.async.commit_group;" ::: "memory")
#define CP_WAIT1()  asm volatile("cp.async.wait_group 1;" ::: "memory")
#define CP_WAIT0()  asm volatile("cp.async.wait_group 0;" ::: "memory")

__device__ __forceinline__ void ldsm4(uint32_t& r0, uint32_t& r1, uint32_t& r2,
                                      uint32_t& r3, uint32_t a) {
    asm volatile("ldmatrix.sync.aligned.m8n8.x4.shared.b16 {%0,%1,%2,%3}, [%4];"
                 : "=r"(r0), "=r"(r1), "=r"(r2), "=r"(r3) : "r"(a));
}
__device__ __forceinline__ void ldsm4t(uint32_t& r0, uint32_t& r1, uint32_t& r2,
                                       uint32_t& r3, uint32_t a) {
    asm volatile("ldmatrix.sync.aligned.m8n8.x4.trans.shared.b16 {%0,%1,%2,%3}, [%4];"
                 : "=r"(r0), "=r"(r1), "=r"(r2), "=r"(r3) : "r"(a));
}
__device__ __forceinline__ void ldsm2(uint32_t& r0, uint32_t& r1, uint32_t a) {
    asm volatile("ldmatrix.sync.aligned.m8n8.x2.shared.b16 {%0,%1}, [%2];"
                 : "=r"(r0), "=r"(r1) : "r"(a));
}
__device__ __forceinline__ void mma_fp(float* c, const uint32_t* a, const uint32_t* b) {
    asm volatile(
        "mma.sync.aligned.m16n8k16.row.col.f32.f16.f16.f32 "
        "{%0,%1,%2,%3}, {%4,%5,%6,%7}, {%8,%9}, {%0,%1,%2,%3};"
        : "+f"(c[0]), "+f"(c[1]), "+f"(c[2]), "+f"(c[3])
        : "r"(a[0]), "r"(a[1]), "r"(a[2]), "r"(a[3]), "r"(b[0]), "r"(b[1]));
}
__device__ __forceinline__ uint32_t pack_h2(float a, float b) {
    __half2 h = __floats2half2_rn(a, b);
    return *reinterpret_cast<uint32_t*>(&h);
}

// ---------------------------------------------------------------------------
// build_idx: deterministic per-batch compaction of valid keys.
// grid = BB, block = 512.  (Runs FIRST — convertA3 consumes g_idx.)
// ---------------------------------------------------------------------------
__global__ __launch_bounds__(512) void build_idx(const int* __restrict__ mask)
{
    __shared__ int wsum[16];
    __shared__ int s_cnt;
    const int b = blockIdx.x, tid = threadIdx.x;
    const int lane = tid & 31, wid = tid >> 5;

    int m[4];
    const int base = b * TT + tid * 4;
    #pragma unroll
    for (int i = 0; i < 4; i++) m[i] = (mask[base + i] != 0) ? 1 : 0;
    const int tot = m[0] + m[1] + m[2] + m[3];

    int scan = tot;
    #pragma unroll
    for (int ofs = 1; ofs < 32; ofs <<= 1) {
        int v = __shfl_up_sync(0xffffffffu, scan, ofs);
        if (lane >= ofs) scan += v;
    }
    if (lane == 31) wsum[wid] = scan;
    __syncthreads();
    if (wid == 0) {
        int v = (lane < 16) ? wsum[lane] : 0;
        #pragma unroll
        for (int ofs = 1; ofs < 16; ofs <<= 1) {
            int t = __shfl_up_sync(0xffffffffu, v, ofs);
            if (lane >= ofs) v += t;
        }
        if (lane < 16) wsum[lane] = v;
        if (lane == 15) s_cnt = v;
    }
    __syncthreads();

    int off = ((wid == 0) ? 0 : wsum[wid - 1]) + scan - tot;
    #pragma unroll
    for (int i = 0; i < 4; i++)
        if (m[i]) g_idx[b * TT + off++] = tid * 4 + i;

    const int cnt = s_cnt;
    #pragma unroll
    for (int i = 0; i < 4; i++) {
        const int j = tid * 4 + i;
        g_vmask[b * TT + j] = (j < cnt) ? 1 : 0;
        if (j >= cnt) g_idx[b * TT + j] = 0;   // padded tail -> row 0 (finite data)
    }
    if (tid == 0) g_ntiles[b] = (cnt + 63) >> 6;
}

// ---------------------------------------------------------------------------
// convertA3: fp32 -> fp16 GEMM A operands.
// z=0: q straight copy.  z=1/2: k/v rows GATHERED through g_idx (compacted).
// grid (MM*DD/1024, 1, 3)
// ---------------------------------------------------------------------------
__global__ __launch_bounds__(256) void convertA3(
    const float* __restrict__ q, const float* __restrict__ k,
    const float* __restrict__ v)
{
    const int z = blockIdx.z;
    const int i = (blockIdx.x * 256 + threadIdx.x) * 4;

    const float* src;
    if (z == 0) {
        src = q + i;
    } else {
        const int row = i >> 10;           // global compacted row (0..MM-1)
        const int b   = row >> 11;         // batch
        const int j   = row & 2047;        // compacted pos in batch
        const int col = i & 1023;
        const int torig = g_idx[b * TT + j];
        const float* base = (z == 1) ? k : v;
        src = base + ((size_t)(b * TT + torig) << 10) + col;
    }
    float4 x = *reinterpret_cast<const float4*>(src);
    uint2 o;
    o.x = pack_h2(x.x, x.y);
    o.y = pack_h2(x.z, x.w);
    *reinterpret_cast<uint2*>(&g_Af[z][i]) = o;
}

// ---------------------------------------------------------------------------
// convertW4: fp32 W[K,N] -> fp16 W^T [N,K], slots 0..3.
// grid (DD/32, DD/32, 4), block (32, 8)
// ---------------------------------------------------------------------------
__global__ __launch_bounds__(256) void convertW4(
    const float* __restrict__ Wq, const float* __restrict__ Wk,
    const float* __restrict__ Wv, const float* __restrict__ Wo)
{
    __shared__ float tile[32][33];
    const int z = blockIdx.z;
    const float* W = (z == 0) ? Wq : (z == 1) ? Wk : (z == 2) ? Wv : Wo;
    const int n0 = blockIdx.x * 32;
    const int k0 = blockIdx.y * 32;
    const int tx = threadIdx.x, ty = threadIdx.y;

    #pragma unroll
    for (int r = 0; r < 4; r++)
        tile[ty + r * 8][tx] = W[(size_t)(k0 + ty + r * 8) * DD + n0 + tx];
    __syncthreads();

    #pragma unroll
    for (int r = 0; r < 4; r++) {
        const int n = ty + r * 8;
        g_Wf[z][(size_t)(n0 + n) * DD + k0 + tx] = __float2half_rn(tile[tx][n]);
    }
}

// ---------------------------------------------------------------------------
// fp16 HMMA GEMM: C[M,N] = A[M,K] @ W^T[N,K] + bias
// 128x128 CTA tile, 8 warps (64x32), BK=32, 3-stage cp.async pipeline.
// final=0: grid (8,32,3) z->q/k/v; K/V CTAs fully in the padded-tail region
// exit immediately (their rows are never read by attention).
// final=1: grid (8,32,1) A slot 0, W slot 3, fp32 out.
// ---------------------------------------------------------------------------
#define TILE_B   10240               // 128 rows * 80 bytes
#define BUF_B    (2 * TILE_B)        // A, B
#define GSM_TOT  (3 * BUF_B)         // 61440, 3 stages

__global__ __launch_bounds__(256, 2) void mma_gemm(
    const float* __restrict__ b0, const float* __restrict__ b1,
    const float* __restrict__ b2, float* __restrict__ Cp, int final_)
{
    extern __shared__ char smem[];
    const uint32_t sb = smem_u32(smem);
    const int tid  = threadIdx.x;
    const int wid  = tid >> 5;
    const int lane = tid & 31;
    const int warp_m = wid & 1;
    const int warp_n = wid >> 1;

    const int z    = final_ ? 0 : blockIdx.z;
    const int ws   = final_ ? 3 : z;
    const int mode = final_ ? 3 : z;    // 0->Qh(/32), 1->Kh, 2->Vf, 3->Cp fp32
    const float* bias = (final_ || z == 0) ? b0 : (z == 1 ? b1 : b2);

    const int aBase = blockIdx.y * 128;

    // K/V projections: skip CTAs entirely inside the padded tail
    if (!final_ && z >= 1) {
        const int bb = aBase >> 11;
        if ((aBase & 2047) >= g_ntiles[bb] * 64) return;
    }

    const int bBase = blockIdx.x * 128;
    const __half* srcA = g_Af[z] + (size_t)aBase * DD;
    const __half* srcW = g_Wf[ws] + (size_t)bBase * DD;

    float acc[4][4][4];
    #pragma unroll
    for (int i = 0; i < 4; i++)
        #pragma unroll
        for (int j = 0; j < 4; j++)
            #pragma unroll
            for (int r = 0; r < 4; r++) acc[i][j][r] = 0.f;

    auto load_chunk = [&](int c, int buf) {
        const int c0 = c * 32;
        const uint32_t base = sb + buf * BUF_B;
        #pragma unroll
        for (int it = 0; it < 4; it++) {
            const int idx = tid + it * 256;        // 0..1023
            const int t2  = idx >> 9;              // 0: A, 1: W
            const int rem = idx & 511;
            const int row = rem >> 2;
            const int seg = rem & 3;
            const __half* s = (t2 == 0) ? srcA : srcW;
            cp16(base + t2 * TILE_B + row * 80 + seg * 16,
                 s + (size_t)row * DD + c0 + seg * 8);
        }
    };

    load_chunk(0, 0); CP_COMMIT();
    load_chunk(1, 1); CP_COMMIT();

    int cb = 0, lb = 2;
    for (int c = 0; c < 32; c++) {
        if (c < 31) { CP_WAIT1(); } else { CP_WAIT0(); }
        __syncthreads();

        if (c + 2 < 32) {
            load_chunk(c + 2, lb);
            CP_COMMIT();
        }

        const uint32_t sA = sb + cb * BUF_B;
        const uint32_t sB = sA + TILE_B;

        #pragma unroll
        for (int ks = 0; ks < 2; ks++) {
            const int kb = ks * 32;
            uint32_t af[4][4], bf[4][2];

            const int arow = (lane & 15);
            const uint32_t acol = ((lane >> 4) << 4) + kb;
            #pragma unroll
            for (int mt = 0; mt < 4; mt++) {
                const uint32_t ro = (uint32_t)(warp_m * 64 + mt * 16 + arow) * 80 + acol;
                ldsm4(af[mt][0], af[mt][1], af[mt][2], af[mt][3], sA + ro);
            }
            const int brow = (lane & 7);
            const uint32_t bcol = (((lane >> 3) & 1) << 4) + kb;
            #pragma unroll
            for (int nt = 0; nt < 4; nt++) {
                const uint32_t ro = (uint32_t)(warp_n * 32 + nt * 8 + brow) * 80 + bcol;
                ldsm2(bf[nt][0], bf[nt][1], sB + ro);
            }

            #pragma unroll
            for (int mt = 0; mt < 4; mt++)
                #pragma unroll
                for (int nt = 0; nt < 4; nt++)
                    mma_fp(acc[mt][nt], af[mt], bf[nt]);
        }

        cb = (cb == 2) ? 0 : cb + 1;
        lb = (lb == 2) ? 0 : lb + 1;
    }

    // ---- epilogue ----
    const float qs = (mode == 0) ? 0.03125f : 1.0f;
    #pragma unroll
    for (int mt = 0; mt < 4; mt++) {
        const int row0 = aBase + warp_m * 64 + mt * 16 + (lane >> 2);
        #pragma unroll
        for (int nt = 0; nt < 4; nt++) {
            const int col = bBase + warp_n * 32 + nt * 8 + (lane & 3) * 2;
            const float bb0 = bias[col], bb1 = bias[col + 1];
            float2 v0 = { acc[mt][nt][0] + bb0, acc[mt][nt][1] + bb1 };
            float2 v1 = { acc[mt][nt][2] + bb0, acc[mt][nt][3] + bb1 };
            if (mode == 3) {
                *reinterpret_cast<float2*>(Cp + (size_t)row0 * DD + col) = v0;
                *reinterpret_cast<float2*>(Cp + (size_t)(row0 + 8) * DD + col) = v1;
            } else {
                __half* D = (mode == 0) ? g_Qh : (mode == 1) ? g_Kh : g_Vf;
                *reinterpret_cast<uint32_t*>(D + (size_t)row0 * DD + col) =
                    pack_h2(v0.x * qs, v0.y * qs);
                *reinterpret_cast<uint32_t*>(D + (size_t)(row0 + 8) * DD + col) =
                    pack_h2(v1.x * qs, v1.y * qs);
            }
        }
    }
}

// ---------------------------------------------------------------------------
// Tensor-core flash attention over COMPACTED keys (fp16, 3-stage pipeline).
// grid = (T/64 qtiles, B*H), block = 128 (4 warps, 16 q-rows each).
// K/V already compacted by the projection — loader is straight rows, no
// gather. V transposed at ldmatrix time (.trans). Output -> g_Af[0] fp16.
// ---------------------------------------------------------------------------
#define APB    144            // smem row pitch bytes (64 halves + pad)
#define OFF_K  0
#define OFF_V  9216
#define OFF_MS 18432
#define ABUF   18688
#define ASM_TOT (3*ABUF)      // 56064, 3 stages

__global__ __launch_bounds__(128) void attn_mma()
{
    extern __shared__ char smema[];
    const uint32_t sb = smem_u32(smema);
    const int tid  = threadIdx.x;
    const int lane = tid & 31;
    const int w    = tid >> 5;
    const int bh   = blockIdx.y;
    const int b    = bh >> 4, h = bh & 15;
    const int q0   = blockIdx.x * 64;
    const int c0   = (lane & 3) * 2;
    const float NEGINF = -__int_as_float(0x7f800000);

    const int ntk = g_ntiles[b];

    // preload Q A-frags (fp16, pre-scaled 1/32)
    uint32_t qa[4][4];
    {
        const int r = q0 + w * 16 + (lane >> 2);
        const __half* Qb = g_Qh + (size_t)(b * TT + r) * DD + h * 64;
        #pragma unroll
        for (int t = 0; t < 4; t++) {
            qa[t][0] = *reinterpret_cast<const uint32_t*>(Qb + t * 16 + c0);
            qa[t][1] = *reinterpret_cast<const uint32_t*>(Qb + 8 * DD + t * 16 + c0);
            qa[t][2] = *reinterpret_cast<const uint32_t*>(Qb + t * 16 + 8 + c0);
            qa[t][3] = *reinterpret_cast<const uint32_t*>(Qb + 8 * DD + t * 16 + 8 + c0);
        }
    }

    auto load_tiles = [&](int kt, int bufsel) {
        const uint32_t base = sb + bufsel * ABUF;
        const int s0 = kt * 64;
        #pragma unroll
        for (int it = 0; it < 4; it++) {
            const int idx = tid + it * 128;       // 0..511
            const int row = idx >> 3, seg = idx & 7;
            const size_t g = (size_t)(b * TT + s0 + row) * DD + h * 64 + seg * 8;
            cp16(base + OFF_K + row * APB + seg * 16, g_Kh + g);
            cp16(base + OFF_V + row * APB + seg * 16, g_Vf + g);
        }
        if (tid < 16) cp16(base + OFF_MS + tid * 16, g_vmask + b * TT + s0 + tid * 4);
    };

    float o[8][4];
    #pragma unroll
    for (int n = 0; n < 8; n++)
        #pragma unroll
        for (int r = 0; r < 4; r++) o[n][r] = 0.f;
    float m0 = -1e30f, m1 = -1e30f, l0 = 0.f, l1 = 0.f;

    load_tiles(0, 0); CP_COMMIT();
    if (ntk > 1) { load_tiles(1, 1); CP_COMMIT(); }

    int cb = 0, lb = 2;
    for (int kt = 0; kt < ntk; kt++) {
        if (kt < ntk - 1) { CP_WAIT1(); } else { CP_WAIT0(); }
        __syncthreads();

        if (kt + 2 < ntk) {
            load_tiles(kt + 2, lb);
            CP_COMMIT();
        }

        const uint32_t base = sb + cb * ABUF;

        // ---- S = Q K^T (fp16, fp32 accum) ----
        float sf[8][4];
        #pragma unroll
        for (int j = 0; j < 8; j++) {
            sf[j][0] = sf[j][1] = sf[j][2] = sf[j][3] = 0.f;
            uint32_t kA[4], kB[4];
            const uint32_t ka = base + OFF_K + (j * 8 + (lane & 7)) * APB
                              + ((lane >> 3) & 3) * 16;
            ldsm4(kA[0], kA[1], kA[2], kA[3], ka);
            ldsm4(kB[0], kB[1], kB[2], kB[3], ka + 64);
            mma_fp(sf[j], qa[0], &kA[0]);
            mma_fp(sf[j], qa[1], &kA[2]);
            mma_fp(sf[j], qa[2], &kB[0]);
            mma_fp(sf[j], qa[3], &kB[2]);
        }

        // ---- mask (incl. padded tail) + online softmax ----
        float p[8][4];
        float mx0 = NEGINF, mx1 = NEGINF;
        #pragma unroll
        for (int j = 0; j < 8; j++) {
            const int2 mk = *reinterpret_cast<const int2*>(
                smema + cb * ABUF + OFF_MS + (j * 8 + c0) * 4);
            sf[j][0] = mk.x ? sf[j][0] : NEGINF;
            sf[j][1] = mk.y ? sf[j][1] : NEGINF;
            sf[j][2] = mk.x ? sf[j][2] : NEGINF;
            sf[j][3] = mk.y ? sf[j][3] : NEGINF;
            mx0 = fmaxf(mx0, fmaxf(sf[j][0], sf[j][1]));
            mx1 = fmaxf(mx1, fmaxf(sf[j][2], sf[j][3]));
        }
        mx0 = fmaxf(mx0, __shfl_xor_sync(0xffffffffu, mx0, 1));
        mx0 = fmaxf(mx0, __shfl_xor_sync(0xffffffffu, mx0, 2));
        mx1 = fmaxf(mx1, __shfl_xor_sync(0xffffffffu, mx1, 1));
        mx1 = fmaxf(mx1, __shfl_xor_sync(0xffffffffu, mx1, 2));

        const float mn0 = fmaxf(m0, mx0), mn1 = fmaxf(m1, mx1);
        const float sc0 = __expf(m0 - mn0), sc1 = __expf(m1 - mn1);
        float sum0 = 0.f, sum1 = 0.f;
        #pragma unroll
        for (int j = 0; j < 8; j++) {
            p[j][0] = __expf(sf[j][0] - mn0);
            p[j][1] = __expf(sf[j][1] - mn0);
            p[j][2] = __expf(sf[j][2] - mn1);
            p[j][3] = __expf(sf[j][3] - mn1);
            sum0 += p[j][0] + p[j][1];
            sum1 += p[j][2] + p[j][3];
        }
        sum0 += __shfl_xor_sync(0xffffffffu, sum0, 1);
        sum0 += __shfl_xor_sync(0xffffffffu, sum0, 2);
        sum1 += __shfl_xor_sync(0xffffffffu, sum1, 1);
        sum1 += __shfl_xor_sync(0xffffffffu, sum1, 2);
        l0 = l0 * sc0 + sum0;
        l1 = l1 * sc1 + sum1;
        m0 = mn0;
        m1 = mn1;
        #pragma unroll
        for (int n = 0; n < 8; n++) {
            o[n][0] *= sc0; o[n][1] *= sc0;
            o[n][2] *= sc1; o[n][3] *= sc1;
        }

        // ---- pack P -> fp16 A-frags ----
        uint32_t pa[4][4];
        #pragma unroll
        for (int t = 0; t < 4; t++) {
            pa[t][0] = pack_h2(p[2*t][0],   p[2*t][1]);
            pa[t][1] = pack_h2(p[2*t][2],   p[2*t][3]);
            pa[t][2] = pack_h2(p[2*t+1][0], p[2*t+1][1]);
            pa[t][3] = pack_h2(p[2*t+1][2], p[2*t+1][3]);
        }

        // ---- O += P V  (V row-major in smem, transposed by ldsm.trans) ----
        #pragma unroll
        for (int n = 0; n < 8; n++) {
            uint32_t vA[4], vB[4];
            const uint32_t va = base + OFF_V + (uint32_t)lane * APB + n * 16;
            ldsm4t(vA[0], vA[1], vA[2], vA[3], va);              // keys 0..31
            ldsm4t(vB[0], vB[1], vB[2], vB[3], va + 32 * APB);   // keys 32..63
            mma_fp(o[n], pa[0], &vA[0]);
            mma_fp(o[n], pa[1], &vA[2]);
            mma_fp(o[n], pa[2], &vB[0]);
            mma_fp(o[n], pa[3], &vB[2]);
        }

        cb = (cb == 2) ? 0 : cb + 1;
        lb = (lb == 2) ? 0 : lb + 1;
    }

    // ---- epilogue: o/l -> fp16 directly into final-GEMM A slot 0 ----
    const float i0 = 1.f / l0, i1 = 1.f / l1;
    const int r0 = q0 + w * 16 + (lane >> 2);
    #pragma unroll
    for (int n = 0; n < 8; n++) {
        const size_t a0 = (size_t)(b * TT + r0) * DD + h * 64 + n * 8 + c0;
        const size_t a1 = a0 + 8 * DD;
        *reinterpret_cast<uint32_t*>(&g_Af[0][a0]) = pack_h2(o[n][0] * i0, o[n][1] * i0);
        *reinterpret_cast<uint32_t*>(&g_Af[0][a1]) = pack_h2(o[n][2] * i1, o[n][3] * i1);
    }
}

// ---------------------------------------------------------------------------
// Launch
// ---------------------------------------------------------------------------
extern "C" void kernel_launch(void* const* d_in, const int* in_sizes, int n_in,
                              void* d_out, int out_size)
{
    const float* q    = (const float*)d_in[0];
    const float* k    = (const float*)d_in[1];
    const float* v    = (const float*)d_in[2];
    const int*   mask = (const int*)  d_in[3];
    const float* Wq   = (const float*)d_in[4];
    const float* bq   = (const float*)d_in[5];
    const float* Wk   = (const float*)d_in[6];
    const float* bk   = (const float*)d_in[7];
    const float* Wv   = (const float*)d_in[8];
    const float* bv   = (const float*)d_in[9];
    const float* Wo   = (const float*)d_in[10];
    const float* bo   = (const float*)d_in[11];
    float* out = (float*)d_out;

    cudaFuncSetAttribute(mma_gemm, cudaFuncAttributeMaxDynamicSharedMemorySize, GSM_TOT);
    cudaFuncSetAttribute(attn_mma, cudaFuncAttributeMaxDynamicSharedMemorySize, ASM_TOT);

    const dim3 cgrid(MM * DD / 4 / 256, 1, 3);
    const dim3 wgrid(DD / 32, DD / 32, 4);
    const dim3 wblk(32, 8);
    const dim3 pgrid(DD / 128, MM / 128, 3);   // batched projections
    const dim3 fgrid(DD / 128, MM / 128, 1);   // final GEMM
    const dim3 agrid(TT / 64, BB * HH);

    build_idx<<<BB, 512>>>(mask);                              // compaction FIRST
    convertW4<<<wgrid, wblk>>>(Wq, Wk, Wv, Wo);                // W^T fp16
    convertA3<<<cgrid, 256>>>(q, k, v);                        // A fp16 (k/v gathered)

    mma_gemm<<<pgrid, 256, GSM_TOT>>>(bq, bk, bv, nullptr, 0); // Qh + compacted Kh/Vf

    attn_mma<<<agrid, 128, ASM_TOT>>>();                       // -> g_Af[0]

    mma_gemm<<<fgrid, 256, GSM_TOT>>>(bo, bo, bo, out, 1);     // -> out
}

// round 13
// speedup vs baseline: 13.5177x; 1.0454x over previous
#include <cuda_runtime.h>
#include <cuda_fp16.h>
#include <cstdint>

#define BB 2
#define TT 2048
#define DD 1024
#define HH 16
#define DH 64
#define MM (BB*TT)   // 4096

// ---------------- scratch (device globals, no runtime alloc) ----------------
__device__ __align__(16) __half g_Af[3][MM*DD];   // GEMM A fp16 per z (slot 0 reused for attn out)
__device__ __align__(16) __half g_Wf[4][DD*DD];   // W^T fp16 [slot][N][K]
__device__ __align__(16) __half g_Qh[MM*DD];      // Q proj fp16 (pre-scaled 1/32)
__device__ __align__(16) __half g_Kh[MM*DD];      // K proj fp16 (COMPACTED rows)
__device__ __align__(16) __half g_Vf[MM*DD];      // V proj fp16 (COMPACTED rows)
__device__ int g_idx[BB*TT];                      // compacted key -> orig t
__device__ __align__(16) int g_vmask[BB*TT];      // 1 if compacted pos valid
__device__ int g_ntiles[BB];                      // ceil(count/64)

// ---------------- PTX helpers (arch-generic sm_80+) ----------
__device__ __forceinline__ uint32_t smem_u32(const void* p) {
    uint32_t a;
    asm("{ .reg .u64 t; cvta.to.shared.u64 t, %1; cvt.u32.u64 %0, t; }" : "=r"(a) : "l"(p));
    return a;
}
__device__ __forceinline__ void cp16(uint32_t s, const void* g) {
    asm volatile("cp.async.cg.shared.global [%0], [%1], 16;" :: "r"(s), "l"(g));
}
#define CP_COMMIT() asm volatile("cp.async.commit_group;" ::: "memory")
#define CP_WAIT1()  asm volatile("cp.async.wait_group 1;" ::: "memory")
#define CP_WAIT0()  asm volatile("cp.async.wait_group 0;" ::: "memory")

__device__ __forceinline__ void ldsm4(uint32_t& r0, uint32_t& r1, uint32_t& r2,
                                      uint32_t& r3, uint32_t a) {
    asm volatile("ldmatrix.sync.aligned.m8n8.x4.shared.b16 {%0,%1,%2,%3}, [%4];"
                 : "=r"(r0), "=r"(r1), "=r"(r2), "=r"(r3) : "r"(a));
}
__device__ __forceinline__ void ldsm4t(uint32_t& r0, uint32_t& r1, uint32_t& r2,
                                       uint32_t& r3, uint32_t a) {
    asm volatile("ldmatrix.sync.aligned.m8n8.x4.trans.shared.b16 {%0,%1,%2,%3}, [%4];"
                 : "=r"(r0), "=r"(r1), "=r"(r2), "=r"(r3) : "r"(a));
}
__device__ __forceinline__ void ldsm2(uint32_t& r0, uint32_t& r1, uint32_t a) {
    asm volatile("ldmatrix.sync.aligned.m8n8.x2.shared.b16 {%0,%1}, [%2];"
                 : "=r"(r0), "=r"(r1) : "r"(a));
}
__device__ __forceinline__ void mma_fp(float* c, const uint32_t* a, const uint32_t* b) {
    asm volatile(
        "mma.sync.aligned.m16n8k16.row.col.f32.f16.f16.f32 "
        "{%0,%1,%2,%3}, {%4,%5,%6,%7}, {%8,%9}, {%0,%1,%2,%3};"
        : "+f"(c[0]), "+f"(c[1]), "+f"(c[2]), "+f"(c[3])
        : "r"(a[0]), "r"(a[1]), "r"(a[2]), "r"(a[3]), "r"(b[0]), "r"(b[1]));
}
__device__ __forceinline__ uint32_t pack_h2(float a, float b) {
    __half2 h = __floats2half2_rn(a, b);
    return *reinterpret_cast<uint32_t*>(&h);
}

// ---------------------------------------------------------------------------
// build_idx: deterministic per-batch compaction of valid keys.
// grid = BB, block = 512.  (Runs FIRST — convertA3 consumes g_idx.)
// ---------------------------------------------------------------------------
__global__ __launch_bounds__(512) void build_idx(const int* __restrict__ mask)
{
    __shared__ int wsum[16];
    __shared__ int s_cnt;
    const int b = blockIdx.x, tid = threadIdx.x;
    const int lane = tid & 31, wid = tid >> 5;

    int m[4];
    const int base = b * TT + tid * 4;
    #pragma unroll
    for (int i = 0; i < 4; i++) m[i] = (mask[base + i] != 0) ? 1 : 0;
    const int tot = m[0] + m[1] + m[2] + m[3];

    int scan = tot;
    #pragma unroll
    for (int ofs = 1; ofs < 32; ofs <<= 1) {
        int v = __shfl_up_sync(0xffffffffu, scan, ofs);
        if (lane >= ofs) scan += v;
    }
    if (lane == 31) wsum[wid] = scan;
    __syncthreads();
    if (wid == 0) {
        int v = (lane < 16) ? wsum[lane] : 0;
        #pragma unroll
        for (int ofs = 1; ofs < 16; ofs <<= 1) {
            int t = __shfl_up_sync(0xffffffffu, v, ofs);
            if (lane >= ofs) v += t;
        }
        if (lane < 16) wsum[lane] = v;
        if (lane == 15) s_cnt = v;
    }
    __syncthreads();

    int off = ((wid == 0) ? 0 : wsum[wid - 1]) + scan - tot;
    #pragma unroll
    for (int i = 0; i < 4; i++)
        if (m[i]) g_idx[b * TT + off++] = tid * 4 + i;

    const int cnt = s_cnt;
    #pragma unroll
    for (int i = 0; i < 4; i++) {
        const int j = tid * 4 + i;
        g_vmask[b * TT + j] = (j < cnt) ? 1 : 0;
        if (j >= cnt) g_idx[b * TT + j] = 0;   // padded tail -> row 0
    }
    if (tid == 0) g_ntiles[b] = (cnt + 63) >> 6;
}

// ---------------------------------------------------------------------------
// convertA3: fp32 -> fp16 GEMM A operands.
// z=0: q straight copy.  z=1/2: k/v rows GATHERED through g_idx (compacted).
// grid (MM*DD/1024, 1, 3)
// ---------------------------------------------------------------------------
__global__ __launch_bounds__(256) void convertA3(
    const float* __restrict__ q, const float* __restrict__ k,
    const float* __restrict__ v)
{
    const int z = blockIdx.z;
    const int i = (blockIdx.x * 256 + threadIdx.x) * 4;

    const float* src;
    if (z == 0) {
        src = q + i;
    } else {
        const int row = i >> 10;
        const int b   = row >> 11;
        const int j   = row & 2047;
        const int col = i & 1023;
        const int torig = g_idx[b * TT + j];
        const float* base = (z == 1) ? k : v;
        src = base + ((size_t)(b * TT + torig) << 10) + col;
    }
    float4 x = *reinterpret_cast<const float4*>(src);
    uint2 o;
    o.x = pack_h2(x.x, x.y);
    o.y = pack_h2(x.z, x.w);
    *reinterpret_cast<uint2*>(&g_Af[z][i]) = o;
}

// ---------------------------------------------------------------------------
// convertW4: fp32 W[K,N] -> fp16 W^T [N,K], slots 0..3.
// grid (DD/32, DD/32, 4), block (32, 8)
// ---------------------------------------------------------------------------
__global__ __launch_bounds__(256) void convertW4(
    const float* __restrict__ Wq, const float* __restrict__ Wk,
    const float* __restrict__ Wv, const float* __restrict__ Wo)
{
    __shared__ float tile[32][33];
    const int z = blockIdx.z;
    const float* W = (z == 0) ? Wq : (z == 1) ? Wk : (z == 2) ? Wv : Wo;
    const int n0 = blockIdx.x * 32;
    const int k0 = blockIdx.y * 32;
    const int tx = threadIdx.x, ty = threadIdx.y;

    #pragma unroll
    for (int r = 0; r < 4; r++)
        tile[ty + r * 8][tx] = W[(size_t)(k0 + ty + r * 8) * DD + n0 + tx];
    __syncthreads();

    #pragma unroll
    for (int r = 0; r < 4; r++) {
        const int n = ty + r * 8;
        g_Wf[z][(size_t)(n0 + n) * DD + k0 + tx] = __float2half_rn(tile[tx][n]);
    }
}

// ---------------------------------------------------------------------------
// fp16 HMMA GEMM: C[M,N] = A[M,K] @ W^T[N,K] + bias
// 128x128 CTA tile, 8 warps (64x32), BK=64 (16 chunks, 16 barriers),
// 3-stage cp.async pipeline. Row pitch 144B -> conflict-free ldmatrix.
// final=0: grid (8,32,3) z->q/k/v; padded-tail K/V CTAs exit early.
// final=1: grid (8,32,1) A slot 0, W slot 3, fp32 out.
// ---------------------------------------------------------------------------
#define GPITCH   144
#define TILE_B   (128 * GPITCH)      // 18432
#define BUF_B    (2 * TILE_B)        // 36864 (A + B)
#define GSM_TOT  (3 * BUF_B)         // 110592, 3 stages

__global__ __launch_bounds__(256, 2) void mma_gemm(
    const float* __restrict__ b0, const float* __restrict__ b1,
    const float* __restrict__ b2, float* __restrict__ Cp, int final_)
{
    extern __shared__ char smem[];
    const uint32_t sb = smem_u32(smem);
    const int tid  = threadIdx.x;
    const int wid  = tid >> 5;
    const int lane = tid & 31;
    const int warp_m = wid & 1;
    const int warp_n = wid >> 1;

    const int z    = final_ ? 0 : blockIdx.z;
    const int ws   = final_ ? 3 : z;
    const int mode = final_ ? 3 : z;    // 0->Qh(/32), 1->Kh, 2->Vf, 3->Cp fp32
    const float* bias = (final_ || z == 0) ? b0 : (z == 1 ? b1 : b2);

    const int aBase = blockIdx.y * 128;

    if (!final_ && z >= 1) {
        const int bb = aBase >> 11;
        if ((aBase & 2047) >= g_ntiles[bb] * 64) return;
    }

    const int bBase = blockIdx.x * 128;
    const __half* srcA = g_Af[z] + (size_t)aBase * DD;
    const __half* srcW = g_Wf[ws] + (size_t)bBase * DD;

    float acc[4][4][4];
    #pragma unroll
    for (int i = 0; i < 4; i++)
        #pragma unroll
        for (int j = 0; j < 4; j++)
            #pragma unroll
            for (int r = 0; r < 4; r++) acc[i][j][r] = 0.f;

    auto load_chunk = [&](int c, int buf) {
        const int c0 = c * 64;
        const uint32_t base = sb + buf * BUF_B;
        #pragma unroll
        for (int it = 0; it < 8; it++) {
            const int idx = tid + it * 256;        // 0..2047
            const int t2  = idx >> 10;             // 0: A, 1: W
            const int rem = idx & 1023;
            const int row = rem >> 3;
            const int seg = rem & 7;
            const __half* s = (t2 == 0) ? srcA : srcW;
            cp16(base + t2 * TILE_B + row * GPITCH + seg * 16,
                 s + (size_t)row * DD + c0 + seg * 8);
        }
    };

    load_chunk(0, 0); CP_COMMIT();
    load_chunk(1, 1); CP_COMMIT();

    int cb = 0, lb = 2;
    for (int c = 0; c < 16; c++) {
        if (c < 15) { CP_WAIT1(); } else { CP_WAIT0(); }
        __syncthreads();

        if (c + 2 < 16) {
            load_chunk(c + 2, lb);
            CP_COMMIT();
        }

        const uint32_t sA = sb + cb * BUF_B;
        const uint32_t sB = sA + TILE_B;

        #pragma unroll
        for (int ks = 0; ks < 4; ks++) {
            const int kb = ks * 32;
            uint32_t af[4][4], bf[4][2];

            const int arow = (lane & 15);
            const uint32_t acol = ((lane >> 4) << 4) + kb;
            #pragma unroll
            for (int mt = 0; mt < 4; mt++) {
                const uint32_t ro = (uint32_t)(warp_m * 64 + mt * 16 + arow) * GPITCH + acol;
                ldsm4(af[mt][0], af[mt][1], af[mt][2], af[mt][3], sA + ro);
            }
            const int brow = (lane & 7);
            const uint32_t bcol = (((lane >> 3) & 1) << 4) + kb;
            #pragma unroll
            for (int nt = 0; nt < 4; nt++) {
                const uint32_t ro = (uint32_t)(warp_n * 32 + nt * 8 + brow) * GPITCH + bcol;
                ldsm2(bf[nt][0], bf[nt][1], sB + ro);
            }

            #pragma unroll
            for (int mt = 0; mt < 4; mt++)
                #pragma unroll
                for (int nt = 0; nt < 4; nt++)
                    mma_fp(acc[mt][nt], af[mt], bf[nt]);
        }

        cb = (cb == 2) ? 0 : cb + 1;
        lb = (lb == 2) ? 0 : lb + 1;
    }

    // ---- epilogue ----
    const float qs = (mode == 0) ? 0.03125f : 1.0f;
    #pragma unroll
    for (int mt = 0; mt < 4; mt++) {
        const int row0 = aBase + warp_m * 64 + mt * 16 + (lane >> 2);
        #pragma unroll
        for (int nt = 0; nt < 4; nt++) {
            const int col = bBase + warp_n * 32 + nt * 8 + (lane & 3) * 2;
            const float bb0 = bias[col], bb1 = bias[col + 1];
            float2 v0 = { acc[mt][nt][0] + bb0, acc[mt][nt][1] + bb1 };
            float2 v1 = { acc[mt][nt][2] + bb0, acc[mt][nt][3] + bb1 };
            if (mode == 3) {
                *reinterpret_cast<float2*>(Cp + (size_t)row0 * DD + col) = v0;
                *reinterpret_cast<float2*>(Cp + (size_t)(row0 + 8) * DD + col) = v1;
            } else {
                __half* D = (mode == 0) ? g_Qh : (mode == 1) ? g_Kh : g_Vf;
                *reinterpret_cast<uint32_t*>(D + (size_t)row0 * DD + col) =
                    pack_h2(v0.x * qs, v0.y * qs);
                *reinterpret_cast<uint32_t*>(D + (size_t)(row0 + 8) * DD + col) =
                    pack_h2(v1.x * qs, v1.y * qs);
            }
        }
    }
}

// ---------------------------------------------------------------------------
// Tensor-core flash attention over COMPACTED keys (fp16, 3-stage pipeline).
// grid = (T/128 qtiles, B*H), block = 256 (8 warps, 16 q-rows each) —
// 128 queries share each K/V tile: halves L2 traffic vs 64-q CTAs.
// V transposed at ldmatrix time (.trans). Output -> g_Af[0] fp16.
// ---------------------------------------------------------------------------
#define APB    144            // smem row pitch bytes (64 halves + pad)
#define OFF_K  0
#define OFF_V  9216
#define OFF_MS 18432
#define ABUF   18688
#define ASM_TOT (3*ABUF)      // 56064, 3 stages

__global__ __launch_bounds__(256, 2) void attn_mma()
{
    extern __shared__ char smema[];
    const uint32_t sb = smem_u32(smema);
    const int tid  = threadIdx.x;
    const int lane = tid & 31;
    const int w    = tid >> 5;          // 0..7
    const int bh   = blockIdx.y;
    const int b    = bh >> 4, h = bh & 15;
    const int q0   = blockIdx.x * 128;
    const int c0   = (lane & 3) * 2;
    const float NEGINF = -__int_as_float(0x7f800000);

    const int ntk = g_ntiles[b];

    // preload Q A-frags (fp16, pre-scaled 1/32)
    uint32_t qa[4][4];
    {
        const int r = q0 + w * 16 + (lane >> 2);
        const __half* Qb = g_Qh + (size_t)(b * TT + r) * DD + h * 64;
        #pragma unroll
        for (int t = 0; t < 4; t++) {
            qa[t][0] = *reinterpret_cast<const uint32_t*>(Qb + t * 16 + c0);
            qa[t][1] = *reinterpret_cast<const uint32_t*>(Qb + 8 * DD + t * 16 + c0);
            qa[t][2] = *reinterpret_cast<const uint32_t*>(Qb + t * 16 + 8 + c0);
            qa[t][3] = *reinterpret_cast<const uint32_t*>(Qb + 8 * DD + t * 16 + 8 + c0);
        }
    }

    auto load_tiles = [&](int kt, int bufsel) {
        const uint32_t base = sb + bufsel * ABUF;
        const int s0 = kt * 64;
        #pragma unroll
        for (int it = 0; it < 2; it++) {
            const int idx = tid + it * 256;       // 0..511
            const int row = idx >> 3, seg = idx & 7;
            const size_t g = (size_t)(b * TT + s0 + row) * DD + h * 64 + seg * 8;
            cp16(base + OFF_K + row * APB + seg * 16, g_Kh + g);
            cp16(base + OFF_V + row * APB + seg * 16, g_Vf + g);
        }
        if (tid < 16) cp16(base + OFF_MS + tid * 16, g_vmask + b * TT + s0 + tid * 4);
    };

    float o[8][4];
    #pragma unroll
    for (int n = 0; n < 8; n++)
        #pragma unroll
        for (int r = 0; r < 4; r++) o[n][r] = 0.f;
    float m0 = -1e30f, m1 = -1e30f, l0 = 0.f, l1 = 0.f;

    load_tiles(0, 0); CP_COMMIT();
    if (ntk > 1) { load_tiles(1, 1); CP_COMMIT(); }

    int cb = 0, lb = 2;
    for (int kt = 0; kt < ntk; kt++) {
        if (kt < ntk - 1) { CP_WAIT1(); } else { CP_WAIT0(); }
        __syncthreads();

        if (kt + 2 < ntk) {
            load_tiles(kt + 2, lb);
            CP_COMMIT();
        }

        const uint32_t base = sb + cb * ABUF;

        // ---- S = Q K^T (fp16, fp32 accum) ----
        float sf[8][4];
        #pragma unroll
        for (int j = 0; j < 8; j++) {
            sf[j][0] = sf[j][1] = sf[j][2] = sf[j][3] = 0.f;
            uint32_t kA[4], kB[4];
            const uint32_t ka = base + OFF_K + (j * 8 + (lane & 7)) * APB
                              + ((lane >> 3) & 3) * 16;
            ldsm4(kA[0], kA[1], kA[2], kA[3], ka);
            ldsm4(kB[0], kB[1], kB[2], kB[3], ka + 64);
            mma_fp(sf[j], qa[0], &kA[0]);
            mma_fp(sf[j], qa[1], &kA[2]);
            mma_fp(sf[j], qa[2], &kB[0]);
            mma_fp(sf[j], qa[3], &kB[2]);
        }

        // ---- mask (incl. padded tail) + online softmax (p in-place in sf) ----
        float mx0 = NEGINF, mx1 = NEGINF;
        #pragma unroll
        for (int j = 0; j < 8; j++) {
            const int2 mk = *reinterpret_cast<const int2*>(
                smema + cb * ABUF + OFF_MS + (j * 8 + c0) * 4);
            sf[j][0] = mk.x ? sf[j][0] : NEGINF;
            sf[j][1] = mk.y ? sf[j][1] : NEGINF;
            sf[j][2] = mk.x ? sf[j][2] : NEGINF;
            sf[j][3] = mk.y ? sf[j][3] : NEGINF;
            mx0 = fmaxf(mx0, fmaxf(sf[j][0], sf[j][1]));
            mx1 = fmaxf(mx1, fmaxf(sf[j][2], sf[j][3]));
        }
        mx0 = fmaxf(mx0, __shfl_xor_sync(0xffffffffu, mx0, 1));
        mx0 = fmaxf(mx0, __shfl_xor_sync(0xffffffffu, mx0, 2));
        mx1 = fmaxf(mx1, __shfl_xor_sync(0xffffffffu, mx1, 1));
        mx1 = fmaxf(mx1, __shfl_xor_sync(0xffffffffu, mx1, 2));

        const float mn0 = fmaxf(m0, mx0), mn1 = fmaxf(m1, mx1);
        const float sc0 = __expf(m0 - mn0), sc1 = __expf(m1 - mn1);
        float sum0 = 0.f, sum1 = 0.f;
        #pragma unroll
        for (int j = 0; j < 8; j++) {
            sf[j][0] = __expf(sf[j][0] - mn0);
            sf[j][1] = __expf(sf[j][1] - mn0);
            sf[j][2] = __expf(sf[j][2] - mn1);
            sf[j][3] = __expf(sf[j][3] - mn1);
            sum0 += sf[j][0] + sf[j][1];
            sum1 += sf[j][2] + sf[j][3];
        }
        sum0 += __shfl_xor_sync(0xffffffffu, sum0, 1);
        sum0 += __shfl_xor_sync(0xffffffffu, sum0, 2);
        sum1 += __shfl_xor_sync(0xffffffffu, sum1, 1);
        sum1 += __shfl_xor_sync(0xffffffffu, sum1, 2);
        l0 = l0 * sc0 + sum0;
        l1 = l1 * sc1 + sum1;
        m0 = mn0;
        m1 = mn1;
        #pragma unroll
        for (int n = 0; n < 8; n++) {
            o[n][0] *= sc0; o[n][1] *= sc0;
            o[n][2] *= sc1; o[n][3] *= sc1;
        }

        // ---- pack P -> fp16 A-frags ----
        uint32_t pa[4][4];
        #pragma unroll
        for (int t = 0; t < 4; t++) {
            pa[t][0] = pack_h2(sf[2*t][0],   sf[2*t][1]);
            pa[t][1] = pack_h2(sf[2*t][2],   sf[2*t][3]);
            pa[t][2] = pack_h2(sf[2*t+1][0], sf[2*t+1][1]);
            pa[t][3] = pack_h2(sf[2*t+1][2], sf[2*t+1][3]);
        }

        // ---- O += P V  (V row-major in smem, transposed by ldsm.trans) ----
        #pragma unroll
        for (int n = 0; n < 8; n++) {
            uint32_t vA[4], vB[4];
            const uint32_t va = base + OFF_V + (uint32_t)lane * APB + n * 16;
            ldsm4t(vA[0], vA[1], vA[2], vA[3], va);              // keys 0..31
            ldsm4t(vB[0], vB[1], vB[2], vB[3], va + 32 * APB);   // keys 32..63
            mma_fp(o[n], pa[0], &vA[0]);
            mma_fp(o[n], pa[1], &vA[2]);
            mma_fp(o[n], pa[2], &vB[0]);
            mma_fp(o[n], pa[3], &vB[2]);
        }

        cb = (cb == 2) ? 0 : cb + 1;
        lb = (lb == 2) ? 0 : lb + 1;
    }

    // ---- epilogue: o/l -> fp16 directly into final-GEMM A slot 0 ----
    const float i0 = 1.f / l0, i1 = 1.f / l1;
    const int r0 = q0 + w * 16 + (lane >> 2);
    #pragma unroll
    for (int n = 0; n < 8; n++) {
        const size_t a0 = (size_t)(b * TT + r0) * DD + h * 64 + n * 8 + c0;
        const size_t a1 = a0 + 8 * DD;
        *reinterpret_cast<uint32_t*>(&g_Af[0][a0]) = pack_h2(o[n][0] * i0, o[n][1] * i0);
        *reinterpret_cast<uint32_t*>(&g_Af[0][a1]) = pack_h2(o[n][2] * i1, o[n][3] * i1);
    }
}

// ---------------------------------------------------------------------------
// Launch
// ---------------------------------------------------------------------------
extern "C" void kernel_launch(void* const* d_in, const int* in_sizes, int n_in,
                              void* d_out, int out_size)
{
    const float* q    = (const float*)d_in[0];
    const float* k    = (const float*)d_in[1];
    const float* v    = (const float*)d_in[2];
    const int*   mask = (const int*)  d_in[3];
    const float* Wq   = (const float*)d_in[4];
    const float* bq   = (const float*)d_in[5];
    const float* Wk   = (const float*)d_in[6];
    const float* bk   = (const float*)d_in[7];
    const float* Wv   = (const float*)d_in[8];
    const float* bv   = (const float*)d_in[9];
    const float* Wo   = (const float*)d_in[10];
    const float* bo   = (const float*)d_in[11];
    float* out = (float*)d_out;

    cudaFuncSetAttribute(mma_gemm, cudaFuncAttributeMaxDynamicSharedMemorySize, GSM_TOT);
    cudaFuncSetAttribute(attn_mma, cudaFuncAttributeMaxDynamicSharedMemorySize, ASM_TOT);

    const dim3 cgrid(MM * DD / 4 / 256, 1, 3);
    const dim3 wgrid(DD / 32, DD / 32, 4);
    const dim3 wblk(32, 8);
    const dim3 pgrid(DD / 128, MM / 128, 3);   // batched projections
    const dim3 fgrid(DD / 128, MM / 128, 1);   // final GEMM
    const dim3 agrid(TT / 128, BB * HH);

    build_idx<<<BB, 512>>>(mask);                              // compaction FIRST
    convertW4<<<wgrid, wblk>>>(Wq, Wk, Wv, Wo);                // W^T fp16
    convertA3<<<cgrid, 256>>>(q, k, v);                        // A fp16 (k/v gathered)

    mma_gemm<<<pgrid, 256, GSM_TOT>>>(bq, bk, bv, nullptr, 0); // Qh + compacted Kh/Vf

    attn_mma<<<agrid, 256, ASM_TOT>>>();                       // -> g_Af[0]

    mma_gemm<<<fgrid, 256, GSM_TOT>>>(bo, bo, bo, out, 1);     // -> out
}